// round 8
// baseline (speedup 1.0000x reference)
#include <cuda_runtime.h>
#include <cuda_fp16.h>
#include <cstdint>

// Problem constants
#define TOK     2048
#define DMODEL  1024
#define DINNER  2048
#define DSTATE  16
#define SEQLEN  1024
#define NBATCH  2
#define NIN     (3 * DINNER)
#define CHK     16
#define CHL     (SEQLEN / CHK)
#define NSLOT   (NBATCH * DINNER)
#define NSS     (NSLOT * DSTATE)

// ---------------------------------------------------------------------------
// Device-global scratch
// ---------------------------------------------------------------------------
__device__ __half g_xproj16[TOK * DINNER];
__device__ __half g_delta16[TOK * DINNER];
__device__ __half g_gate16 [TOK * DINNER];

__device__ __half g_a16[(size_t)TOK * DINNER * DSTATE];  // per-step decay factors
__device__ __half g_u16[TOK * DINNER];                   // dt * xt

__device__ float g_P [CHK * NSS];
__device__ float g_q [CHK * NSS];
__device__ float g_h0[CHK * NSS];

__device__ __half g_x  [TOK * DMODEL];
__device__ __half g_wi [NIN * DMODEL];
__device__ __half g_wo [DMODEL * DINNER];
__device__ __half g_gss[TOK * DINNER];

// ---------------------------------------------------------------------------
// PTX helpers
// ---------------------------------------------------------------------------
__device__ __forceinline__ uint32_t smem_u32(const void* p) {
    uint32_t a;
    asm("{ .reg .u64 t; cvta.to.shared.u64 t, %1; cvt.u32.u64 %0, t; }" : "=r"(a) : "l"(p));
    return a;
}
__device__ __forceinline__ void cpa16(uint32_t s, const void* g) {
    asm volatile("cp.async.cg.shared.global [%0], [%1], 16;" :: "r"(s), "l"(g) : "memory");
}
__device__ __forceinline__ void cpa_commit() {
    asm volatile("cp.async.commit_group;" ::: "memory");
}
template <int N>
__device__ __forceinline__ void cpa_wait() {
    asm volatile("cp.async.wait_group %0;" :: "n"(N) : "memory");
}
__device__ __forceinline__ void ldsm4(uint32_t& r0, uint32_t& r1, uint32_t& r2,
                                      uint32_t& r3, uint32_t a) {
    asm volatile("ldmatrix.sync.aligned.m8n8.x4.shared.b16 {%0,%1,%2,%3}, [%4];"
                 : "=r"(r0), "=r"(r1), "=r"(r2), "=r"(r3) : "r"(a));
}
__device__ __forceinline__ void mma16816(float* d, const uint32_t* a, const uint32_t* b) {
    asm volatile(
        "mma.sync.aligned.m16n8k16.row.col.f32.f16.f16.f32 "
        "{%0,%1,%2,%3}, {%4,%5,%6,%7}, {%8,%9}, {%0,%1,%2,%3};"
        : "+f"(d[0]), "+f"(d[1]), "+f"(d[2]), "+f"(d[3])
        : "r"(a[0]), "r"(a[1]), "r"(a[2]), "r"(a[3]), "r"(b[0]), "r"(b[1]));
}

// Fast exp on FMA/ALU pipes (GEMM epilogue sigmoid only)
__device__ __forceinline__ float fexp(float z) {
    float nf = rintf(z * 1.4426950408889634f);
    float r  = fmaf(nf, -0.693145751953125f, z);
    r        = fmaf(nf, -1.42860677e-6f, r);
    float p  = 1.0f / 720.0f;
    p = fmaf(p, r, 1.0f / 120.0f);
    p = fmaf(p, r, 1.0f / 24.0f);
    p = fmaf(p, r, 1.0f / 6.0f);
    p = fmaf(p, r, 0.5f);
    p = fmaf(p, r, 1.0f);
    p = fmaf(p, r, 1.0f);
    float s = __int_as_float(((int)nf + 127) << 23);
    return p * s;
}

// ---------------------------------------------------------------------------
// SMEM: stage = A (BM rows) ++ W (128 rows), 80B rows, double buffered
// ---------------------------------------------------------------------------
#define ROWB 80
#define SMEMT(BM) (2 * ((BM) * ROWB + 128 * ROWB) + 512)

template <int ROWS>
__device__ __forceinline__ void tile_cpasync(const __half* __restrict__ g,
                                             int rowBase, int kt, int ld,
                                             uint32_t sdst, int tid) {
#pragma unroll
    for (int i = 0; i < ROWS / 64; i++) {
        int seg = tid + i * 256;
        int r   = seg >> 2;
        int c   = seg & 3;
        cpa16(sdst + r * ROWB + c * 16,
              g + (size_t)(rowBase + r) * ld + kt + c * 8);
    }
}

// ---------------------------------------------------------------------------
// fp16 GEMM: C = A @ W^T + bias
// EPI 0 (N=6144): xproj16 | relu->delta16 | sigmoid->gate16 (fp16 stores)
// EPI 2: +bias -> Cout (fp32)
// ---------------------------------------------------------------------------
template <int EPI, int BM>
__global__ void __launch_bounds__(256, 2)
gemm_mma(const __half* __restrict__ A, const __half* __restrict__ W,
         const float* __restrict__ biasA, const float* __restrict__ biasB,
         float* __restrict__ Cout, int N, int K)
{
    constexpr int MI     = BM / 32;
    constexpr int ATILE  = BM * ROWB;
    constexpr int BTILE  = 128 * ROWB;
    constexpr int STAGE  = ATILE + BTILE;
    constexpr int BIASOF = 2 * STAGE;

    extern __shared__ char smem[];
    uint32_t sbase = smem_u32(smem);

    const int tid = threadIdx.x;
    const int wid = tid >> 5;
    const int l   = tid & 31;
    const int wm  = wid >> 2;
    const int wn  = wid & 3;
    const int mo  = wm * (BM / 2);
    const int no  = wn * 32;

    const int rowBase = blockIdx.y * BM;
    const int colBase = blockIdx.x * 128;

    if (tid < 128) {
        float bv;
        if (EPI == 0)
            bv = (colBase < 2 * DINNER) ? biasA[colBase + tid]
                                        : biasB[colBase - 2 * DINNER + tid];
        else
            bv = biasA[colBase + tid];
        *reinterpret_cast<float*>(smem + BIASOF + tid * 4) = bv;
    }

    const uint32_t aRow = (uint32_t)((mo + (l & 15)) * ROWB + ((l >> 4) * 16));
    const uint32_t bRow = (uint32_t)((no + (l & 7) + ((l & 16) ? 8 : 0)) * ROWB
                                     + (((l >> 3) & 1) * 16));

    float acc[MI][4][4];
#pragma unroll
    for (int mi = 0; mi < MI; mi++)
#pragma unroll
        for (int ni = 0; ni < 4; ni++)
#pragma unroll
            for (int r = 0; r < 4; r++) acc[mi][ni][r] = 0.0f;

    const int NC = K / 32;

    {
        uint32_t st = sbase;
        tile_cpasync<BM >(A, rowBase, 0, K, st,         tid);
        tile_cpasync<128>(W, colBase, 0, K, st + ATILE, tid);
        cpa_commit();
    }

    for (int c = 0; c < NC; c++) {
        if (c + 1 < NC) {
            uint32_t st = sbase + ((c + 1) & 1) * STAGE;
            int kt = (c + 1) * 32;
            tile_cpasync<BM >(A, rowBase, kt, K, st,         tid);
            tile_cpasync<128>(W, colBase, kt, K, st + ATILE, tid);
            cpa_commit();
            cpa_wait<1>();
        } else {
            cpa_wait<0>();
        }
        __syncthreads();

        uint32_t st = sbase + (c & 1) * STAGE;
#pragma unroll
        for (int ks = 0; ks < 2; ks++) {
            uint32_t ah[MI][4], bh[8];
#pragma unroll
            for (int mi = 0; mi < MI; mi++) {
                uint32_t ad = st + aRow + mi * (16 * ROWB) + ks * 32;
                ldsm4(ah[mi][0], ah[mi][1], ah[mi][2], ah[mi][3], ad);
            }
#pragma unroll
            for (int np = 0; np < 2; np++) {
                uint32_t bd = st + ATILE + bRow + np * (16 * ROWB) + ks * 32;
                ldsm4(bh[np * 4 + 0], bh[np * 4 + 1], bh[np * 4 + 2], bh[np * 4 + 3], bd);
            }
#pragma unroll
            for (int mi = 0; mi < MI; mi++)
#pragma unroll
                for (int ni = 0; ni < 4; ni++)
                    mma16816(acc[mi][ni], ah[mi], &bh[ni * 2]);
        }
        __syncthreads();
    }

    const float* sb = reinterpret_cast<const float*>(smem + BIASOF);
    const int g  = l >> 2;
    const int t4 = l & 3;
#pragma unroll
    for (int mi = 0; mi < MI; mi++) {
#pragma unroll
        for (int ni = 0; ni < 4; ni++) {
            int bc   = no + ni * 8 + 2 * t4;
            int col  = colBase + bc;
            int row0 = rowBase + mo + mi * 16 + g;
            int row1 = row0 + 8;
            float2 v0, v1;
            v0.x = acc[mi][ni][0] + sb[bc];
            v0.y = acc[mi][ni][1] + sb[bc + 1];
            v1.x = acc[mi][ni][2] + sb[bc];
            v1.y = acc[mi][ni][3] + sb[bc + 1];
            if (EPI == 0) {
                if (colBase < DINNER) {
                    __half2 h0 = __floats2half2_rn(v0.x, v0.y);
                    __half2 h1 = __floats2half2_rn(v1.x, v1.y);
                    *reinterpret_cast<__half2*>(&g_xproj16[(size_t)row0 * DINNER + col]) = h0;
                    *reinterpret_cast<__half2*>(&g_xproj16[(size_t)row1 * DINNER + col]) = h1;
                } else if (colBase < 2 * DINNER) {
                    int cc = col - DINNER;
                    __half2 h0 = __floats2half2_rn(fmaxf(v0.x, 0.f), fmaxf(v0.y, 0.f));
                    __half2 h1 = __floats2half2_rn(fmaxf(v1.x, 0.f), fmaxf(v1.y, 0.f));
                    *reinterpret_cast<__half2*>(&g_delta16[(size_t)row0 * DINNER + cc]) = h0;
                    *reinterpret_cast<__half2*>(&g_delta16[(size_t)row1 * DINNER + cc]) = h1;
                } else {
                    int cc = col - 2 * DINNER;
                    __half2 h0 = __floats2half2_rn(1.f / (1.f + fexp(-v0.x)),
                                                   1.f / (1.f + fexp(-v0.y)));
                    __half2 h1 = __floats2half2_rn(1.f / (1.f + fexp(-v1.x)),
                                                   1.f / (1.f + fexp(-v1.y)));
                    *reinterpret_cast<__half2*>(&g_gate16[(size_t)row0 * DINNER + cc]) = h0;
                    *reinterpret_cast<__half2*>(&g_gate16[(size_t)row1 * DINNER + cc]) = h1;
                }
            } else {
                *reinterpret_cast<float2*>(&Cout[(size_t)row0 * N + col]) = v0;
                *reinterpret_cast<float2*>(&Cout[(size_t)row1 * N + col]) = v1;
            }
        }
    }
}

// fp32 -> fp16 convert (8 elems / thread)
__global__ void __launch_bounds__(256)
conv8_kernel(const float4* __restrict__ src, uint4* __restrict__ dst, int n8)
{
    int i = blockIdx.x * blockDim.x + threadIdx.x;
    if (i >= n8) return;
    float4 u = src[2 * i];
    float4 v = src[2 * i + 1];
    __half2 h0 = __floats2half2_rn(u.x, u.y);
    __half2 h1 = __floats2half2_rn(u.z, u.w);
    __half2 h2 = __floats2half2_rn(v.x, v.y);
    __half2 h3 = __floats2half2_rn(v.z, v.w);
    uint4 o;
    o.x = *reinterpret_cast<uint32_t*>(&h0);
    o.y = *reinterpret_cast<uint32_t*>(&h1);
    o.z = *reinterpret_cast<uint32_t*>(&h2);
    o.w = *reinterpret_cast<uint32_t*>(&h3);
    dst[i] = o;
}

// ---------------------------------------------------------------------------
// Chunked selective scan.
// Phase A: compute (P, q); STORE a=exp(As*dt) (fp16) and u=dt*xt (fp16).
// Phase B: compose chunk-initial states h0.
// Phase C: replay recurrence from stored a/u (NO exp), reduce, gate, emit fp16.
// ---------------------------------------------------------------------------
__global__ void __launch_bounds__(256)
scanA_kernel(const float* __restrict__ A_log, const float* __restrict__ B_mat)
{
    int gidx  = blockIdx.x * 16 + (threadIdx.x >> 4);
    int s     = threadIdx.x & 15;
    int chunk = gidx >> 12;
    int slot  = gidx & (NSLOT - 1);
    int b     = slot >> 11;
    int ch    = slot & (DINNER - 1);

    float As = -__expf(A_log[ch * DSTATE + s]);
    float Bs = B_mat[ch * DSTATE + s];

    float P = 1.0f, q = 0.0f;
    size_t base = (size_t)(b * SEQLEN + chunk * CHL) * DINNER + ch;

#pragma unroll 4
    for (int t = 0; t < CHL; t++) {
        size_t idx = base + (size_t)t * DINNER;
        float dt = __half2float(g_delta16[idx]);
        float xt = __half2float(g_xproj16[idx]);
        float a  = __expf(As * dt);
        float u  = dt * xt;
        g_a16[idx * DSTATE + s] = __float2half(a);
        if (s == 0) g_u16[idx] = __float2half(u);
        q = fmaf(q, a, u * Bs);
        P *= a;
    }
    g_P[(size_t)gidx * DSTATE + s] = P;
    g_q[(size_t)gidx * DSTATE + s] = q;
}

__global__ void __launch_bounds__(256)
scanB_kernel()
{
    int i = blockIdx.x * 256 + threadIdx.x;
    float h = 0.0f;
#pragma unroll
    for (int k = 0; k < CHK; k++) {
        g_h0[(size_t)k * NSS + i] = h;
        h = fmaf(g_P[(size_t)k * NSS + i], h, g_q[(size_t)k * NSS + i]);
    }
}

__global__ void __launch_bounds__(256)
scanC_kernel(const float* __restrict__ B_mat, const float* __restrict__ C_mat,
             const float* __restrict__ D_vec)
{
    int gidx  = blockIdx.x * 16 + (threadIdx.x >> 4);
    int s     = threadIdx.x & 15;
    int chunk = gidx >> 12;
    int slot  = gidx & (NSLOT - 1);
    int b     = slot >> 11;
    int ch    = slot & (DINNER - 1);

    float Bs  = B_mat[ch * DSTATE + s];
    float cs  = C_mat[s];
    float Dch = D_vec[ch];

    float h = g_h0[(size_t)gidx * DSTATE + s];
    size_t base = (size_t)(b * SEQLEN + chunk * CHL) * DINNER + ch;

#pragma unroll 4
    for (int t = 0; t < CHL; t++) {
        size_t idx = base + (size_t)t * DINNER;
        float a = __half2float(g_a16[idx * DSTATE + s]);
        float u = __half2float(g_u16[idx]);
        h = fmaf(h, a, u * Bs);
        float p = h * cs;
        p += __shfl_xor_sync(0xffffffffu, p, 1);
        p += __shfl_xor_sync(0xffffffffu, p, 2);
        p += __shfl_xor_sync(0xffffffffu, p, 4);
        p += __shfl_xor_sync(0xffffffffu, p, 8);
        if (s == 0) {
            float xt = __half2float(g_xproj16[idx]);
            float gg = __half2float(g_gate16[idx]);
            float v  = gg * (p + xt * Dch);
            g_gss[idx] = __float2half(v);
        }
    }
}

// ---------------------------------------------------------------------------
extern "C" void kernel_launch(void* const* d_in, const int* in_sizes, int n_in,
                              void* d_out, int out_size)
{
    const float* x      = (const float*)d_in[0];
    const float* W_in   = (const float*)d_in[1];
    const float* b_in   = (const float*)d_in[2];
    const float* W_gate = (const float*)d_in[3];
    const float* b_gate = (const float*)d_in[4];
    const float* W_out  = (const float*)d_in[5];
    const float* b_out  = (const float*)d_in[6];
    const float* A_log  = (const float*)d_in[7];
    const float* B_mat  = (const float*)d_in[8];
    const float* C_mat  = (const float*)d_in[9];
    const float* D_vec  = (const float*)d_in[10];
    float* out = (float*)d_out;

    cudaFuncSetAttribute((const void*)gemm_mma<0, 128>,
                         cudaFuncAttributeMaxDynamicSharedMemorySize, SMEMT(128));
    cudaFuncSetAttribute((const void*)gemm_mma<2, 64>,
                         cudaFuncAttributeMaxDynamicSharedMemorySize, SMEMT(64));

    __half *xh, *wi, *wo, *gs;
    cudaGetSymbolAddress((void**)&xh, g_x);
    cudaGetSymbolAddress((void**)&wi, g_wi);
    cudaGetSymbolAddress((void**)&wo, g_wo);
    cudaGetSymbolAddress((void**)&gs, g_gss);

    const size_t WG_OFF = (size_t)2 * DINNER * DMODEL;

    // 1) fp32 -> fp16 converts
    {
        int n;
        n = TOK * DMODEL;
        conv8_kernel<<<(n / 8 + 255) / 256, 256>>>((const float4*)x, (uint4*)xh, n / 8);
        n = 2 * DINNER * DMODEL;
        conv8_kernel<<<(n / 8 + 255) / 256, 256>>>((const float4*)W_in, (uint4*)wi, n / 8);
        n = DINNER * DMODEL;
        conv8_kernel<<<(n / 8 + 255) / 256, 256>>>((const float4*)W_gate, (uint4*)(wi + WG_OFF), n / 8);
        n = DMODEL * DINNER;
        conv8_kernel<<<(n / 8 + 255) / 256, 256>>>((const float4*)W_out, (uint4*)wo, n / 8);
    }

    // 2) fused in-proj + gate GEMM (N = 6144), fp16 epilogue
    gemm_mma<0, 128><<<dim3(NIN / 128, TOK / 128), 256, SMEMT(128)>>>(
        xh, wi, b_in, b_gate, nullptr, NIN, DMODEL);

    // 3) chunked selective scan (phase C exp-free)
    scanA_kernel<<<4096, 256>>>(A_log, B_mat);
    scanB_kernel<<<NSS / 256, 256>>>();
    scanC_kernel<<<4096, 256>>>(B_mat, C_mat, D_vec);

    // 4) out = gss @ W_out^T + b_out  (BM=64 -> 256 CTAs)
    gemm_mma<2, 64><<<dim3(DMODEL / 128, TOK / 64), 256, SMEMT(64)>>>(
        gs, wo, b_out, nullptr, out, DMODEL, DINNER);
}

// round 9
// speedup vs baseline: 1.1910x; 1.1910x over previous
#include <cuda_runtime.h>
#include <cuda_fp16.h>
#include <cstdint>

// Problem constants
#define TOK     2048
#define DMODEL  1024
#define DINNER  2048
#define DSTATE  16
#define SEQLEN  1024
#define NBATCH  2
#define NIN     (3 * DINNER)
#define CHK     16
#define CHL     (SEQLEN / CHK)
#define NSLOT   (NBATCH * DINNER)
#define NSS     (NSLOT * DSTATE)

// ---------------------------------------------------------------------------
// Device-global scratch
// ---------------------------------------------------------------------------
__device__ __half g_xproj16[TOK * DINNER];
__device__ __half g_delta16[TOK * DINNER];
__device__ __half g_gate16 [TOK * DINNER];

__device__ float g_P [CHK * NSS];
__device__ float g_q [CHK * NSS];
__device__ float g_h0[CHK * NSS];

__device__ __half g_x  [TOK * DMODEL];
__device__ __half g_wi [NIN * DMODEL];
__device__ __half g_wo [DMODEL * DINNER];
__device__ __half g_gss[TOK * DINNER];

// ---------------------------------------------------------------------------
// PTX helpers
// ---------------------------------------------------------------------------
__device__ __forceinline__ uint32_t smem_u32(const void* p) {
    uint32_t a;
    asm("{ .reg .u64 t; cvta.to.shared.u64 t, %1; cvt.u32.u64 %0, t; }" : "=r"(a) : "l"(p));
    return a;
}
__device__ __forceinline__ void cpa16(uint32_t s, const void* g) {
    asm volatile("cp.async.cg.shared.global [%0], [%1], 16;" :: "r"(s), "l"(g) : "memory");
}
__device__ __forceinline__ void cpa_commit() {
    asm volatile("cp.async.commit_group;" ::: "memory");
}
template <int N>
__device__ __forceinline__ void cpa_wait() {
    asm volatile("cp.async.wait_group %0;" :: "n"(N) : "memory");
}
__device__ __forceinline__ void ldsm4(uint32_t& r0, uint32_t& r1, uint32_t& r2,
                                      uint32_t& r3, uint32_t a) {
    asm volatile("ldmatrix.sync.aligned.m8n8.x4.shared.b16 {%0,%1,%2,%3}, [%4];"
                 : "=r"(r0), "=r"(r1), "=r"(r2), "=r"(r3) : "r"(a));
}
__device__ __forceinline__ void mma16816(float* d, const uint32_t* a, const uint32_t* b) {
    asm volatile(
        "mma.sync.aligned.m16n8k16.row.col.f32.f16.f16.f32 "
        "{%0,%1,%2,%3}, {%4,%5,%6,%7}, {%8,%9}, {%0,%1,%2,%3};"
        : "+f"(d[0]), "+f"(d[1]), "+f"(d[2]), "+f"(d[3])
        : "r"(a[0]), "r"(a[1]), "r"(a[2]), "r"(a[3]), "r"(b[0]), "r"(b[1]));
}

// Fast exp on FMA/ALU pipes (GEMM epilogue sigmoid only)
__device__ __forceinline__ float fexp(float z) {
    float nf = rintf(z * 1.4426950408889634f);
    float r  = fmaf(nf, -0.693145751953125f, z);
    r        = fmaf(nf, -1.42860677e-6f, r);
    float p  = 1.0f / 720.0f;
    p = fmaf(p, r, 1.0f / 120.0f);
    p = fmaf(p, r, 1.0f / 24.0f);
    p = fmaf(p, r, 1.0f / 6.0f);
    p = fmaf(p, r, 0.5f);
    p = fmaf(p, r, 1.0f);
    p = fmaf(p, r, 1.0f);
    float s = __int_as_float(((int)nf + 127) << 23);
    return p * s;
}

// ---------------------------------------------------------------------------
// SMEM: stage = A (BM rows) ++ W (128 rows), 80B rows, double buffered
// ---------------------------------------------------------------------------
#define ROWB 80
#define SMEMT(BM) (2 * ((BM) * ROWB + 128 * ROWB) + 512)

template <int ROWS>
__device__ __forceinline__ void tile_cpasync(const __half* __restrict__ g,
                                             int rowBase, int kt, int ld,
                                             uint32_t sdst, int tid) {
#pragma unroll
    for (int i = 0; i < ROWS / 64; i++) {
        int seg = tid + i * 256;
        int r   = seg >> 2;
        int c   = seg & 3;
        cpa16(sdst + r * ROWB + c * 16,
              g + (size_t)(rowBase + r) * ld + kt + c * 8);
    }
}

// ---------------------------------------------------------------------------
// fp16 GEMM: C = A @ W^T + bias
// EPI 0 (N=6144): xproj16 | relu->delta16 | sigmoid->gate16 (fp16 stores)
// EPI 2: +bias -> Cout (fp32)
// ---------------------------------------------------------------------------
template <int EPI, int BM>
__global__ void __launch_bounds__(256, 2)
gemm_mma(const __half* __restrict__ A, const __half* __restrict__ W,
         const float* __restrict__ biasA, const float* __restrict__ biasB,
         float* __restrict__ Cout, int N, int K)
{
    constexpr int MI     = BM / 32;
    constexpr int ATILE  = BM * ROWB;
    constexpr int BTILE  = 128 * ROWB;
    constexpr int STAGE  = ATILE + BTILE;
    constexpr int BIASOF = 2 * STAGE;

    extern __shared__ char smem[];
    uint32_t sbase = smem_u32(smem);

    const int tid = threadIdx.x;
    const int wid = tid >> 5;
    const int l   = tid & 31;
    const int wm  = wid >> 2;
    const int wn  = wid & 3;
    const int mo  = wm * (BM / 2);
    const int no  = wn * 32;

    const int rowBase = blockIdx.y * BM;
    const int colBase = blockIdx.x * 128;

    if (tid < 128) {
        float bv;
        if (EPI == 0)
            bv = (colBase < 2 * DINNER) ? biasA[colBase + tid]
                                        : biasB[colBase - 2 * DINNER + tid];
        else
            bv = biasA[colBase + tid];
        *reinterpret_cast<float*>(smem + BIASOF + tid * 4) = bv;
    }

    const uint32_t aRow = (uint32_t)((mo + (l & 15)) * ROWB + ((l >> 4) * 16));
    const uint32_t bRow = (uint32_t)((no + (l & 7) + ((l & 16) ? 8 : 0)) * ROWB
                                     + (((l >> 3) & 1) * 16));

    float acc[MI][4][4];
#pragma unroll
    for (int mi = 0; mi < MI; mi++)
#pragma unroll
        for (int ni = 0; ni < 4; ni++)
#pragma unroll
            for (int r = 0; r < 4; r++) acc[mi][ni][r] = 0.0f;

    const int NC = K / 32;

    {
        uint32_t st = sbase;
        tile_cpasync<BM >(A, rowBase, 0, K, st,         tid);
        tile_cpasync<128>(W, colBase, 0, K, st + ATILE, tid);
        cpa_commit();
    }

    for (int c = 0; c < NC; c++) {
        if (c + 1 < NC) {
            uint32_t st = sbase + ((c + 1) & 1) * STAGE;
            int kt = (c + 1) * 32;
            tile_cpasync<BM >(A, rowBase, kt, K, st,         tid);
            tile_cpasync<128>(W, colBase, kt, K, st + ATILE, tid);
            cpa_commit();
            cpa_wait<1>();
        } else {
            cpa_wait<0>();
        }
        __syncthreads();

        uint32_t st = sbase + (c & 1) * STAGE;
#pragma unroll
        for (int ks = 0; ks < 2; ks++) {
            uint32_t ah[MI][4], bh[8];
#pragma unroll
            for (int mi = 0; mi < MI; mi++) {
                uint32_t ad = st + aRow + mi * (16 * ROWB) + ks * 32;
                ldsm4(ah[mi][0], ah[mi][1], ah[mi][2], ah[mi][3], ad);
            }
#pragma unroll
            for (int np = 0; np < 2; np++) {
                uint32_t bd = st + ATILE + bRow + np * (16 * ROWB) + ks * 32;
                ldsm4(bh[np * 4 + 0], bh[np * 4 + 1], bh[np * 4 + 2], bh[np * 4 + 3], bd);
            }
#pragma unroll
            for (int mi = 0; mi < MI; mi++)
#pragma unroll
                for (int ni = 0; ni < 4; ni++)
                    mma16816(acc[mi][ni], ah[mi], &bh[ni * 2]);
        }
        __syncthreads();
    }

    const float* sb = reinterpret_cast<const float*>(smem + BIASOF);
    const int g  = l >> 2;
    const int t4 = l & 3;
#pragma unroll
    for (int mi = 0; mi < MI; mi++) {
#pragma unroll
        for (int ni = 0; ni < 4; ni++) {
            int bc   = no + ni * 8 + 2 * t4;
            int col  = colBase + bc;
            int row0 = rowBase + mo + mi * 16 + g;
            int row1 = row0 + 8;
            float2 v0, v1;
            v0.x = acc[mi][ni][0] + sb[bc];
            v0.y = acc[mi][ni][1] + sb[bc + 1];
            v1.x = acc[mi][ni][2] + sb[bc];
            v1.y = acc[mi][ni][3] + sb[bc + 1];
            if (EPI == 0) {
                if (colBase < DINNER) {
                    __half2 h0 = __floats2half2_rn(v0.x, v0.y);
                    __half2 h1 = __floats2half2_rn(v1.x, v1.y);
                    *reinterpret_cast<__half2*>(&g_xproj16[(size_t)row0 * DINNER + col]) = h0;
                    *reinterpret_cast<__half2*>(&g_xproj16[(size_t)row1 * DINNER + col]) = h1;
                } else if (colBase < 2 * DINNER) {
                    int cc = col - DINNER;
                    __half2 h0 = __floats2half2_rn(fmaxf(v0.x, 0.f), fmaxf(v0.y, 0.f));
                    __half2 h1 = __floats2half2_rn(fmaxf(v1.x, 0.f), fmaxf(v1.y, 0.f));
                    *reinterpret_cast<__half2*>(&g_delta16[(size_t)row0 * DINNER + cc]) = h0;
                    *reinterpret_cast<__half2*>(&g_delta16[(size_t)row1 * DINNER + cc]) = h1;
                } else {
                    int cc = col - 2 * DINNER;
                    __half2 h0 = __floats2half2_rn(1.f / (1.f + fexp(-v0.x)),
                                                   1.f / (1.f + fexp(-v0.y)));
                    __half2 h1 = __floats2half2_rn(1.f / (1.f + fexp(-v1.x)),
                                                   1.f / (1.f + fexp(-v1.y)));
                    *reinterpret_cast<__half2*>(&g_gate16[(size_t)row0 * DINNER + cc]) = h0;
                    *reinterpret_cast<__half2*>(&g_gate16[(size_t)row1 * DINNER + cc]) = h1;
                }
            } else {
                *reinterpret_cast<float2*>(&Cout[(size_t)row0 * N + col]) = v0;
                *reinterpret_cast<float2*>(&Cout[(size_t)row1 * N + col]) = v1;
            }
        }
    }
}

// ---------------------------------------------------------------------------
// Fused fp32 -> fp16 convert for all four source arrays (one launch)
// ---------------------------------------------------------------------------
#define CR0 (TOK * DMODEL / 8)               // x
#define CR1 (2 * DINNER * DMODEL / 8)        // W_in
#define CR2 (DINNER * DMODEL / 8)            // W_gate
#define CR3 (DMODEL * DINNER / 8)            // W_out
#define CRT (CR0 + CR1 + CR2 + CR3)

__global__ void __launch_bounds__(256)
conv_all_kernel(const float4* __restrict__ sx, const float4* __restrict__ swi,
                const float4* __restrict__ swg, const float4* __restrict__ swo,
                uint4* __restrict__ dx, uint4* __restrict__ dwi,
                uint4* __restrict__ dwg, uint4* __restrict__ dwo)
{
    int i = blockIdx.x * blockDim.x + threadIdx.x;
    if (i >= CRT) return;
    const float4* s; uint4* d; int off;
    if (i < CR0)                   { s = sx;  d = dx;  off = i; }
    else if (i < CR0 + CR1)        { s = swi; d = dwi; off = i - CR0; }
    else if (i < CR0 + CR1 + CR2)  { s = swg; d = dwg; off = i - CR0 - CR1; }
    else                           { s = swo; d = dwo; off = i - CR0 - CR1 - CR2; }
    float4 u = s[2 * off];
    float4 v = s[2 * off + 1];
    __half2 h0 = __floats2half2_rn(u.x, u.y);
    __half2 h1 = __floats2half2_rn(u.z, u.w);
    __half2 h2 = __floats2half2_rn(v.x, v.y);
    __half2 h3 = __floats2half2_rn(v.z, v.w);
    uint4 o;
    o.x = *reinterpret_cast<uint32_t*>(&h0);
    o.y = *reinterpret_cast<uint32_t*>(&h1);
    o.z = *reinterpret_cast<uint32_t*>(&h2);
    o.w = *reinterpret_cast<uint32_t*>(&h3);
    d[off] = o;
}

// ---------------------------------------------------------------------------
// Chunked selective scan, 4 states per lane (4-lane groups per slot-chunk).
// Phase A: (P, q) per chunk.  Phase B: compose h0.  Phase C: replay + gate.
// ---------------------------------------------------------------------------
__global__ void __launch_bounds__(256)
scanA_kernel(const float* __restrict__ A_log, const float* __restrict__ B_mat)
{
    int grp   = blockIdx.x * 64 + (threadIdx.x >> 2);   // 0..65535
    int s2    = threadIdx.x & 3;
    int chunk = grp >> 12;
    int slot  = grp & (NSLOT - 1);
    int b     = slot >> 11;
    int ch    = slot & (DINNER - 1);

    float As[4], Bs[4];
#pragma unroll
    for (int j = 0; j < 4; j++) {
        int s = s2 * 4 + j;
        As[j] = -__expf(A_log[ch * DSTATE + s]);
        Bs[j] = B_mat[ch * DSTATE + s];
    }

    float P[4] = {1.f, 1.f, 1.f, 1.f};
    float q[4] = {0.f, 0.f, 0.f, 0.f};
    size_t base = (size_t)(b * SEQLEN + chunk * CHL) * DINNER + ch;

#pragma unroll 4
    for (int t = 0; t < CHL; t++) {
        size_t idx = base + (size_t)t * DINNER;
        float dt = __half2float(g_delta16[idx]);
        float xt = __half2float(g_xproj16[idx]);
        float u  = dt * xt;
#pragma unroll
        for (int j = 0; j < 4; j++) {
            float a = __expf(As[j] * dt);
            q[j] = fmaf(q[j], a, u * Bs[j]);
            P[j] *= a;
        }
    }
    size_t o = (size_t)grp * DSTATE + s2 * 4;
    *reinterpret_cast<float4*>(&g_P[o]) = make_float4(P[0], P[1], P[2], P[3]);
    *reinterpret_cast<float4*>(&g_q[o]) = make_float4(q[0], q[1], q[2], q[3]);
}

__global__ void __launch_bounds__(256)
scanB_kernel()
{
    int i = blockIdx.x * 256 + threadIdx.x;   // 0..65535 = slot*16+s
    float h = 0.0f;
#pragma unroll
    for (int k = 0; k < CHK; k++) {
        g_h0[(size_t)k * NSS + i] = h;
        h = fmaf(g_P[(size_t)k * NSS + i], h, g_q[(size_t)k * NSS + i]);
    }
}

__global__ void __launch_bounds__(256)
scanC_kernel(const float* __restrict__ A_log, const float* __restrict__ B_mat,
             const float* __restrict__ C_mat, const float* __restrict__ D_vec)
{
    int grp   = blockIdx.x * 64 + (threadIdx.x >> 2);
    int s2    = threadIdx.x & 3;
    int chunk = grp >> 12;
    int slot  = grp & (NSLOT - 1);
    int b     = slot >> 11;
    int ch    = slot & (DINNER - 1);

    float As[4], Bs[4], cs[4];
#pragma unroll
    for (int j = 0; j < 4; j++) {
        int s = s2 * 4 + j;
        As[j] = -__expf(A_log[ch * DSTATE + s]);
        Bs[j] = B_mat[ch * DSTATE + s];
        cs[j] = C_mat[s];
    }
    float Dch = D_vec[ch];

    float4 h4 = *reinterpret_cast<const float4*>(&g_h0[(size_t)grp * DSTATE + s2 * 4]);
    float h[4] = {h4.x, h4.y, h4.z, h4.w};

    size_t base = (size_t)(b * SEQLEN + chunk * CHL) * DINNER + ch;

#pragma unroll 4
    for (int t = 0; t < CHL; t++) {
        size_t idx = base + (size_t)t * DINNER;
        float dt = __half2float(g_delta16[idx]);
        float xt = __half2float(g_xproj16[idx]);
        float u  = dt * xt;
        float p  = 0.f;
#pragma unroll
        for (int j = 0; j < 4; j++) {
            float a = __expf(As[j] * dt);
            h[j] = fmaf(h[j], a, u * Bs[j]);
            p = fmaf(h[j], cs[j], p);
        }
        p += __shfl_xor_sync(0xffffffffu, p, 1);
        p += __shfl_xor_sync(0xffffffffu, p, 2);
        if (s2 == 0) {
            float gg = __half2float(g_gate16[idx]);
            float v  = gg * (p + xt * Dch);
            g_gss[idx] = __float2half(v);
        }
    }
}

// ---------------------------------------------------------------------------
extern "C" void kernel_launch(void* const* d_in, const int* in_sizes, int n_in,
                              void* d_out, int out_size)
{
    const float* x      = (const float*)d_in[0];
    const float* W_in   = (const float*)d_in[1];
    const float* b_in   = (const float*)d_in[2];
    const float* W_gate = (const float*)d_in[3];
    const float* b_gate = (const float*)d_in[4];
    const float* W_out  = (const float*)d_in[5];
    const float* b_out  = (const float*)d_in[6];
    const float* A_log  = (const float*)d_in[7];
    const float* B_mat  = (const float*)d_in[8];
    const float* C_mat  = (const float*)d_in[9];
    const float* D_vec  = (const float*)d_in[10];
    float* out = (float*)d_out;

    cudaFuncSetAttribute((const void*)gemm_mma<0, 128>,
                         cudaFuncAttributeMaxDynamicSharedMemorySize, SMEMT(128));
    cudaFuncSetAttribute((const void*)gemm_mma<2, 64>,
                         cudaFuncAttributeMaxDynamicSharedMemorySize, SMEMT(64));

    __half *xh, *wi, *wo, *gs;
    cudaGetSymbolAddress((void**)&xh, g_x);
    cudaGetSymbolAddress((void**)&wi, g_wi);
    cudaGetSymbolAddress((void**)&wo, g_wo);
    cudaGetSymbolAddress((void**)&gs, g_gss);

    const size_t WG_OFF = (size_t)2 * DINNER * DMODEL;

    // 1) fused fp32 -> fp16 converts (single launch)
    conv_all_kernel<<<(CRT + 255) / 256, 256>>>(
        (const float4*)x, (const float4*)W_in, (const float4*)W_gate, (const float4*)W_out,
        (uint4*)xh, (uint4*)wi, (uint4*)(wi + WG_OFF), (uint4*)wo);

    // 2) fused in-proj + gate GEMM (N = 6144), fp16 epilogue
    gemm_mma<0, 128><<<dim3(NIN / 128, TOK / 128), 256, SMEMT(128)>>>(
        xh, wi, b_in, b_gate, nullptr, NIN, DMODEL);

    // 3) chunked selective scan (4 states per lane)
    scanA_kernel<<<1024, 256>>>(A_log, B_mat);
    scanB_kernel<<<NSS / 256, 256>>>();
    scanC_kernel<<<1024, 256>>>(A_log, B_mat, C_mat, D_vec);

    // 4) out = gss @ W_out^T + b_out  (BM=64 -> 256 CTAs)
    gemm_mma<2, 64><<<dim3(DMODEL / 128, TOK / 64), 256, SMEMT(64)>>>(
        gs, wo, b_out, nullptr, out, DMODEL, DINNER);
}

// round 10
// speedup vs baseline: 1.4802x; 1.2428x over previous
#include <cuda_runtime.h>
#include <cuda_fp16.h>
#include <cstdint>

// Problem constants
#define TOK     2048
#define DMODEL  1024
#define DINNER  2048
#define DSTATE  16
#define SEQLEN  1024
#define NBATCH  2
#define NIN     (3 * DINNER)
#define CHK     16
#define CHL     (SEQLEN / CHK)
#define NSLOT   (NBATCH * DINNER)
#define NSS     (NSLOT * DSTATE)

// ---------------------------------------------------------------------------
// Device-global scratch
// ---------------------------------------------------------------------------
__device__ float g_xproj[TOK * DINNER];
__device__ float g_delta[TOK * DINNER];
__device__ float g_gate [TOK * DINNER];

__device__ float g_P [CHK * NSS];
__device__ float g_q [CHK * NSS];
__device__ float g_h0[CHK * NSS];

__device__ __half g_x  [TOK * DMODEL];
__device__ __half g_wi [NIN * DMODEL];
__device__ __half g_wo [DMODEL * DINNER];
__device__ __half g_gss[TOK * DINNER];

// ---------------------------------------------------------------------------
// PTX helpers
// ---------------------------------------------------------------------------
__device__ __forceinline__ uint32_t smem_u32(const void* p) {
    uint32_t a;
    asm("{ .reg .u64 t; cvta.to.shared.u64 t, %1; cvt.u32.u64 %0, t; }" : "=r"(a) : "l"(p));
    return a;
}
__device__ __forceinline__ void cpa16(uint32_t s, const void* g) {
    asm volatile("cp.async.cg.shared.global [%0], [%1], 16;" :: "r"(s), "l"(g) : "memory");
}
__device__ __forceinline__ void cpa_commit() {
    asm volatile("cp.async.commit_group;" ::: "memory");
}
template <int N>
__device__ __forceinline__ void cpa_wait() {
    asm volatile("cp.async.wait_group %0;" :: "n"(N) : "memory");
}
__device__ __forceinline__ void ldsm4(uint32_t& r0, uint32_t& r1, uint32_t& r2,
                                      uint32_t& r3, uint32_t a) {
    asm volatile("ldmatrix.sync.aligned.m8n8.x4.shared.b16 {%0,%1,%2,%3}, [%4];"
                 : "=r"(r0), "=r"(r1), "=r"(r2), "=r"(r3) : "r"(a));
}
__device__ __forceinline__ void mma16816(float* d, const uint32_t* a, const uint32_t* b) {
    asm volatile(
        "mma.sync.aligned.m16n8k16.row.col.f32.f16.f16.f32 "
        "{%0,%1,%2,%3}, {%4,%5,%6,%7}, {%8,%9}, {%0,%1,%2,%3};"
        : "+f"(d[0]), "+f"(d[1]), "+f"(d[2]), "+f"(d[3])
        : "r"(a[0]), "r"(a[1]), "r"(a[2]), "r"(a[3]), "r"(b[0]), "r"(b[1]));
}

// Fast exp on FMA/ALU pipes (GEMM epilogue sigmoid only)
__device__ __forceinline__ float fexp(float z) {
    float nf = rintf(z * 1.4426950408889634f);
    float r  = fmaf(nf, -0.693145751953125f, z);
    r        = fmaf(nf, -1.42860677e-6f, r);
    float p  = 1.0f / 720.0f;
    p = fmaf(p, r, 1.0f / 120.0f);
    p = fmaf(p, r, 1.0f / 24.0f);
    p = fmaf(p, r, 1.0f / 6.0f);
    p = fmaf(p, r, 0.5f);
    p = fmaf(p, r, 1.0f);
    p = fmaf(p, r, 1.0f);
    float s = __int_as_float(((int)nf + 127) << 23);
    return p * s;
}

// ---------------------------------------------------------------------------
// SMEM: stage = A (BM rows) ++ W (128 rows), 80B rows, TRIPLE buffered
// ---------------------------------------------------------------------------
#define ROWB 80
#define SMEMT(BM) (3 * ((BM) * ROWB + 128 * ROWB) + 512)

template <int ROWS>
__device__ __forceinline__ void tile_cpasync(const __half* __restrict__ g,
                                             int rowBase, int kt, int ld,
                                             uint32_t sdst, int tid) {
#pragma unroll
    for (int i = 0; i < ROWS / 64; i++) {
        int seg = tid + i * 256;
        int r   = seg >> 2;
        int c   = seg & 3;
        cpa16(sdst + r * ROWB + c * 16,
              g + (size_t)(rowBase + r) * ld + kt + c * 8);
    }
}

// ---------------------------------------------------------------------------
// fp16 GEMM: C = A @ W^T + bias ; 3-stage cp.async pipeline
// EPI 0 (N=6144): xproj | relu->delta | sigmoid->gate (fp32 stores)
// EPI 2: +bias -> Cout (fp32)
// ---------------------------------------------------------------------------
template <int EPI, int BM>
__global__ void __launch_bounds__(256, 2)
gemm_mma(const __half* __restrict__ A, const __half* __restrict__ W,
         const float* __restrict__ biasA, const float* __restrict__ biasB,
         float* __restrict__ Cout, int N, int K)
{
    constexpr int MI     = BM / 32;
    constexpr int ATILE  = BM * ROWB;
    constexpr int BTILE  = 128 * ROWB;
    constexpr int STAGE  = ATILE + BTILE;
    constexpr int BIASOF = 3 * STAGE;

    extern __shared__ char smem[];
    uint32_t sbase = smem_u32(smem);

    const int tid = threadIdx.x;
    const int wid = tid >> 5;
    const int l   = tid & 31;
    const int wm  = wid >> 2;
    const int wn  = wid & 3;
    const int mo  = wm * (BM / 2);
    const int no  = wn * 32;

    const int rowBase = blockIdx.y * BM;
    const int colBase = blockIdx.x * 128;

    if (tid < 128) {
        float bv;
        if (EPI == 0)
            bv = (colBase < 2 * DINNER) ? biasA[colBase + tid]
                                        : biasB[colBase - 2 * DINNER + tid];
        else
            bv = biasA[colBase + tid];
        *reinterpret_cast<float*>(smem + BIASOF + tid * 4) = bv;
    }

    const uint32_t aRow = (uint32_t)((mo + (l & 15)) * ROWB + ((l >> 4) * 16));
    const uint32_t bRow = (uint32_t)((no + (l & 7) + ((l & 16) ? 8 : 0)) * ROWB
                                     + (((l >> 3) & 1) * 16));

    float acc[MI][4][4];
#pragma unroll
    for (int mi = 0; mi < MI; mi++)
#pragma unroll
        for (int ni = 0; ni < 4; ni++)
#pragma unroll
            for (int r = 0; r < 4; r++) acc[mi][ni][r] = 0.0f;

    const int NC = K / 32;

    // prologue: chunks 0 and 1 into stages 0 and 1
    {
        tile_cpasync<BM >(A, rowBase, 0, K, sbase,         tid);
        tile_cpasync<128>(W, colBase, 0, K, sbase + ATILE, tid);
        cpa_commit();
        tile_cpasync<BM >(A, rowBase, 32, K, sbase + STAGE,         tid);
        tile_cpasync<128>(W, colBase, 32, K, sbase + STAGE + ATILE, tid);
        cpa_commit();
    }

    for (int c = 0; c < NC; c++) {
        if (c + 2 < NC) {
            uint32_t st = sbase + ((c + 2) % 3) * STAGE;
            int kt = (c + 2) * 32;
            tile_cpasync<BM >(A, rowBase, kt, K, st,         tid);
            tile_cpasync<128>(W, colBase, kt, K, st + ATILE, tid);
            cpa_commit();
            cpa_wait<2>();
        } else if (c + 1 < NC) {
            cpa_wait<1>();
        } else {
            cpa_wait<0>();
        }
        __syncthreads();

        uint32_t st = sbase + (c % 3) * STAGE;
#pragma unroll
        for (int ks = 0; ks < 2; ks++) {
            uint32_t ah[MI][4], bh[8];
#pragma unroll
            for (int mi = 0; mi < MI; mi++) {
                uint32_t ad = st + aRow + mi * (16 * ROWB) + ks * 32;
                ldsm4(ah[mi][0], ah[mi][1], ah[mi][2], ah[mi][3], ad);
            }
#pragma unroll
            for (int np = 0; np < 2; np++) {
                uint32_t bd = st + ATILE + bRow + np * (16 * ROWB) + ks * 32;
                ldsm4(bh[np * 4 + 0], bh[np * 4 + 1], bh[np * 4 + 2], bh[np * 4 + 3], bd);
            }
#pragma unroll
            for (int mi = 0; mi < MI; mi++)
#pragma unroll
                for (int ni = 0; ni < 4; ni++)
                    mma16816(acc[mi][ni], ah[mi], &bh[ni * 2]);
        }
        __syncthreads();
    }

    const float* sb = reinterpret_cast<const float*>(smem + BIASOF);
    const int g  = l >> 2;
    const int t4 = l & 3;
#pragma unroll
    for (int mi = 0; mi < MI; mi++) {
#pragma unroll
        for (int ni = 0; ni < 4; ni++) {
            int bc   = no + ni * 8 + 2 * t4;
            int col  = colBase + bc;
            int row0 = rowBase + mo + mi * 16 + g;
            int row1 = row0 + 8;
            float2 v0, v1;
            v0.x = acc[mi][ni][0] + sb[bc];
            v0.y = acc[mi][ni][1] + sb[bc + 1];
            v1.x = acc[mi][ni][2] + sb[bc];
            v1.y = acc[mi][ni][3] + sb[bc + 1];
            if (EPI == 0) {
                if (colBase < DINNER) {
                    *reinterpret_cast<float2*>(&g_xproj[(size_t)row0 * DINNER + col]) = v0;
                    *reinterpret_cast<float2*>(&g_xproj[(size_t)row1 * DINNER + col]) = v1;
                } else if (colBase < 2 * DINNER) {
                    v0.x = fmaxf(v0.x, 0.f); v0.y = fmaxf(v0.y, 0.f);
                    v1.x = fmaxf(v1.x, 0.f); v1.y = fmaxf(v1.y, 0.f);
                    int cc = col - DINNER;
                    *reinterpret_cast<float2*>(&g_delta[(size_t)row0 * DINNER + cc]) = v0;
                    *reinterpret_cast<float2*>(&g_delta[(size_t)row1 * DINNER + cc]) = v1;
                } else {
                    v0.x = 1.f / (1.f + fexp(-v0.x));
                    v0.y = 1.f / (1.f + fexp(-v0.y));
                    v1.x = 1.f / (1.f + fexp(-v1.x));
                    v1.y = 1.f / (1.f + fexp(-v1.y));
                    int cc = col - 2 * DINNER;
                    *reinterpret_cast<float2*>(&g_gate[(size_t)row0 * DINNER + cc]) = v0;
                    *reinterpret_cast<float2*>(&g_gate[(size_t)row1 * DINNER + cc]) = v1;
                }
            } else {
                *reinterpret_cast<float2*>(&Cout[(size_t)row0 * N + col]) = v0;
                *reinterpret_cast<float2*>(&Cout[(size_t)row1 * N + col]) = v1;
            }
        }
    }
}

// ---------------------------------------------------------------------------
// Fused fp32 -> fp16 convert for all four source arrays (one launch)
// ---------------------------------------------------------------------------
#define CR0 (TOK * DMODEL / 8)               // x
#define CR1 (2 * DINNER * DMODEL / 8)        // W_in
#define CR2 (DINNER * DMODEL / 8)            // W_gate
#define CR3 (DMODEL * DINNER / 8)            // W_out
#define CRT (CR0 + CR1 + CR2 + CR3)

__global__ void __launch_bounds__(256)
conv_all_kernel(const float4* __restrict__ sx, const float4* __restrict__ swi,
                const float4* __restrict__ swg, const float4* __restrict__ swo,
                uint4* __restrict__ dx, uint4* __restrict__ dwi,
                uint4* __restrict__ dwg, uint4* __restrict__ dwo)
{
    int i = blockIdx.x * blockDim.x + threadIdx.x;
    if (i >= CRT) return;
    const float4* s; uint4* d; int off;
    if (i < CR0)                   { s = sx;  d = dx;  off = i; }
    else if (i < CR0 + CR1)        { s = swi; d = dwi; off = i - CR0; }
    else if (i < CR0 + CR1 + CR2)  { s = swg; d = dwg; off = i - CR0 - CR1; }
    else                           { s = swo; d = dwo; off = i - CR0 - CR1 - CR2; }
    float4 u = s[2 * off];
    float4 v = s[2 * off + 1];
    __half2 h0 = __floats2half2_rn(u.x, u.y);
    __half2 h1 = __floats2half2_rn(u.z, u.w);
    __half2 h2 = __floats2half2_rn(v.x, v.y);
    __half2 h3 = __floats2half2_rn(v.z, v.w);
    uint4 o;
    o.x = *reinterpret_cast<uint32_t*>(&h0);
    o.y = *reinterpret_cast<uint32_t*>(&h1);
    o.z = *reinterpret_cast<uint32_t*>(&h2);
    o.w = *reinterpret_cast<uint32_t*>(&h3);
    d[off] = o;
}

// ---------------------------------------------------------------------------
// Chunked selective scan (round-7 proven layout: 16 lanes per slot-chunk)
// ---------------------------------------------------------------------------
__global__ void __launch_bounds__(256)
scanA_kernel(const float* __restrict__ A_log, const float* __restrict__ B_mat)
{
    int gidx  = blockIdx.x * 16 + (threadIdx.x >> 4);
    int s     = threadIdx.x & 15;
    int chunk = gidx >> 12;
    int slot  = gidx & (NSLOT - 1);
    int b     = slot >> 11;
    int ch    = slot & (DINNER - 1);

    float As = -__expf(A_log[ch * DSTATE + s]);
    float Bs = B_mat[ch * DSTATE + s];

    float P = 1.0f, q = 0.0f;
    size_t base = (size_t)(b * SEQLEN + chunk * CHL) * DINNER + ch;

#pragma unroll 4
    for (int t = 0; t < CHL; t++) {
        size_t idx = base + (size_t)t * DINNER;
        float dt = g_delta[idx];
        float xt = g_xproj[idx];
        float a  = __expf(As * dt);
        q = fmaf(q, a, (dt * xt) * Bs);
        P *= a;
    }
    g_P[(size_t)gidx * DSTATE + s] = P;
    g_q[(size_t)gidx * DSTATE + s] = q;
}

__global__ void __launch_bounds__(256)
scanB_kernel()
{
    int i = blockIdx.x * 256 + threadIdx.x;   // 0..65535 = slot*16+s
    float P[CHK], q[CHK];
#pragma unroll
    for (int k = 0; k < CHK; k++) {
        P[k] = g_P[(size_t)k * NSS + i];
        q[k] = g_q[(size_t)k * NSS + i];
    }
    float h = 0.0f;
#pragma unroll
    for (int k = 0; k < CHK; k++) {
        g_h0[(size_t)k * NSS + i] = h;
        h = fmaf(P[k], h, q[k]);
    }
}

__global__ void __launch_bounds__(256)
scanC_kernel(const float* __restrict__ A_log, const float* __restrict__ B_mat,
             const float* __restrict__ C_mat, const float* __restrict__ D_vec)
{
    int gidx  = blockIdx.x * 16 + (threadIdx.x >> 4);
    int s     = threadIdx.x & 15;
    int chunk = gidx >> 12;
    int slot  = gidx & (NSLOT - 1);
    int b     = slot >> 11;
    int ch    = slot & (DINNER - 1);

    float As  = -__expf(A_log[ch * DSTATE + s]);
    float Bs  = B_mat[ch * DSTATE + s];
    float cs  = C_mat[s];
    float Dch = D_vec[ch];

    float h = g_h0[(size_t)gidx * DSTATE + s];
    size_t base = (size_t)(b * SEQLEN + chunk * CHL) * DINNER + ch;

#pragma unroll 4
    for (int t = 0; t < CHL; t++) {
        size_t idx = base + (size_t)t * DINNER;
        float dt = g_delta[idx];
        float xt = g_xproj[idx];
        float a  = __expf(As * dt);
        h = fmaf(h, a, (dt * xt) * Bs);
        float p = h * cs;
        p += __shfl_xor_sync(0xffffffffu, p, 1);
        p += __shfl_xor_sync(0xffffffffu, p, 2);
        p += __shfl_xor_sync(0xffffffffu, p, 4);
        p += __shfl_xor_sync(0xffffffffu, p, 8);
        if (s == 0) {
            float v = g_gate[idx] * (p + xt * Dch);
            g_gss[idx] = __float2half(v);
        }
    }
}

// ---------------------------------------------------------------------------
extern "C" void kernel_launch(void* const* d_in, const int* in_sizes, int n_in,
                              void* d_out, int out_size)
{
    const float* x      = (const float*)d_in[0];
    const float* W_in   = (const float*)d_in[1];
    const float* b_in   = (const float*)d_in[2];
    const float* W_gate = (const float*)d_in[3];
    const float* b_gate = (const float*)d_in[4];
    const float* W_out  = (const float*)d_in[5];
    const float* b_out  = (const float*)d_in[6];
    const float* A_log  = (const float*)d_in[7];
    const float* B_mat  = (const float*)d_in[8];
    const float* C_mat  = (const float*)d_in[9];
    const float* D_vec  = (const float*)d_in[10];
    float* out = (float*)d_out;

    cudaFuncSetAttribute((const void*)gemm_mma<0, 128>,
                         cudaFuncAttributeMaxDynamicSharedMemorySize, SMEMT(128));
    cudaFuncSetAttribute((const void*)gemm_mma<2, 64>,
                         cudaFuncAttributeMaxDynamicSharedMemorySize, SMEMT(64));

    __half *xh, *wi, *wo, *gs;
    cudaGetSymbolAddress((void**)&xh, g_x);
    cudaGetSymbolAddress((void**)&wi, g_wi);
    cudaGetSymbolAddress((void**)&wo, g_wo);
    cudaGetSymbolAddress((void**)&gs, g_gss);

    const size_t WG_OFF = (size_t)2 * DINNER * DMODEL;

    // 1) fused fp32 -> fp16 converts (single launch)
    conv_all_kernel<<<(CRT + 255) / 256, 256>>>(
        (const float4*)x, (const float4*)W_in, (const float4*)W_gate, (const float4*)W_out,
        (uint4*)xh, (uint4*)wi, (uint4*)(wi + WG_OFF), (uint4*)wo);

    // 2) fused in-proj + gate GEMM (N = 6144)
    gemm_mma<0, 128><<<dim3(NIN / 128, TOK / 128), 256, SMEMT(128)>>>(
        xh, wi, b_in, b_gate, nullptr, NIN, DMODEL);

    // 3) chunked selective scan (round-7 layout)
    scanA_kernel<<<4096, 256>>>(A_log, B_mat);
    scanB_kernel<<<NSS / 256, 256>>>();
    scanC_kernel<<<4096, 256>>>(A_log, B_mat, C_mat, D_vec);

    // 4) out = gss @ W_out^T + b_out  (BM=64 -> 256 CTAs)
    gemm_mma<2, 64><<<dim3(DMODEL / 128, TOK / 64), 256, SMEMT(64)>>>(
        gs, wo, b_out, nullptr, out, DMODEL, DINNER);
}

// round 11
// speedup vs baseline: 1.6977x; 1.1469x over previous
#include <cuda_runtime.h>
#include <cuda_fp16.h>
#include <cstdint>

// Problem constants
#define TOK     2048
#define DMODEL  1024
#define DINNER  2048
#define DSTATE  16
#define SEQLEN  1024
#define NBATCH  2
#define NIN     (3 * DINNER)
#define CHK     16
#define CHL     (SEQLEN / CHK)
#define NSLOT   (NBATCH * DINNER)
#define NSS     (NSLOT * DSTATE)

// ---------------------------------------------------------------------------
// Device-global scratch
// ---------------------------------------------------------------------------
__device__ float g_xproj[TOK * DINNER];
__device__ float g_delta[TOK * DINNER];
__device__ float g_gate [TOK * DINNER];

__device__ float g_P [CHK * NSS];
__device__ float g_q [CHK * NSS];
__device__ float g_h0[CHK * NSS];

__device__ __half g_x  [TOK * DMODEL];
__device__ __half g_wi [NIN * DMODEL];
__device__ __half g_wo [DMODEL * DINNER];
__device__ __half g_gss[TOK * DINNER];

// ---------------------------------------------------------------------------
// PTX helpers
// ---------------------------------------------------------------------------
__device__ __forceinline__ uint32_t smem_u32(const void* p) {
    uint32_t a;
    asm("{ .reg .u64 t; cvta.to.shared.u64 t, %1; cvt.u32.u64 %0, t; }" : "=r"(a) : "l"(p));
    return a;
}
__device__ __forceinline__ void cpa16(uint32_t s, const void* g) {
    asm volatile("cp.async.cg.shared.global [%0], [%1], 16;" :: "r"(s), "l"(g) : "memory");
}
__device__ __forceinline__ void cpa_commit() {
    asm volatile("cp.async.commit_group;" ::: "memory");
}
template <int N>
__device__ __forceinline__ void cpa_wait() {
    asm volatile("cp.async.wait_group %0;" :: "n"(N) : "memory");
}
__device__ __forceinline__ void ldsm4(uint32_t& r0, uint32_t& r1, uint32_t& r2,
                                      uint32_t& r3, uint32_t a) {
    asm volatile("ldmatrix.sync.aligned.m8n8.x4.shared.b16 {%0,%1,%2,%3}, [%4];"
                 : "=r"(r0), "=r"(r1), "=r"(r2), "=r"(r3) : "r"(a));
}
__device__ __forceinline__ void mma16816(float* d, const uint32_t* a, const uint32_t* b) {
    asm volatile(
        "mma.sync.aligned.m16n8k16.row.col.f32.f16.f16.f32 "
        "{%0,%1,%2,%3}, {%4,%5,%6,%7}, {%8,%9}, {%0,%1,%2,%3};"
        : "+f"(d[0]), "+f"(d[1]), "+f"(d[2]), "+f"(d[3])
        : "r"(a[0]), "r"(a[1]), "r"(a[2]), "r"(a[3]), "r"(b[0]), "r"(b[1]));
}

// Fast exp on FMA/ALU pipes (GEMM epilogue sigmoid only)
__device__ __forceinline__ float fexp(float z) {
    float nf = rintf(z * 1.4426950408889634f);
    float r  = fmaf(nf, -0.693145751953125f, z);
    r        = fmaf(nf, -1.42860677e-6f, r);
    float p  = 1.0f / 720.0f;
    p = fmaf(p, r, 1.0f / 120.0f);
    p = fmaf(p, r, 1.0f / 24.0f);
    p = fmaf(p, r, 1.0f / 6.0f);
    p = fmaf(p, r, 0.5f);
    p = fmaf(p, r, 1.0f);
    p = fmaf(p, r, 1.0f);
    float s = __int_as_float(((int)nf + 127) << 23);
    return p * s;
}

// ---------------------------------------------------------------------------
// SMEM: stage = A (BM rows) ++ W (128 rows), 80B rows, TRIPLE buffered
// ---------------------------------------------------------------------------
#define ROWB 80
#define SMEMT(BM) (3 * ((BM) * ROWB + 128 * ROWB) + 512)

template <int ROWS>
__device__ __forceinline__ void tile_cpasync(const __half* __restrict__ g,
                                             int rowBase, int kt, int ld,
                                             uint32_t sdst, int tid) {
#pragma unroll
    for (int i = 0; i < ROWS / 64; i++) {
        int seg = tid + i * 256;
        int r   = seg >> 2;
        int c   = seg & 3;
        cpa16(sdst + r * ROWB + c * 16,
              g + (size_t)(rowBase + r) * ld + kt + c * 8);
    }
}

// ---------------------------------------------------------------------------
// fp16 GEMM: C = A @ W^T + bias ; 3-stage cp.async pipeline
// ---------------------------------------------------------------------------
template <int EPI, int BM>
__global__ void __launch_bounds__(256, 2)
gemm_mma(const __half* __restrict__ A, const __half* __restrict__ W,
         const float* __restrict__ biasA, const float* __restrict__ biasB,
         float* __restrict__ Cout, int N, int K)
{
    constexpr int MI     = BM / 32;
    constexpr int ATILE  = BM * ROWB;
    constexpr int BTILE  = 128 * ROWB;
    constexpr int STAGE  = ATILE + BTILE;
    constexpr int BIASOF = 3 * STAGE;

    extern __shared__ char smem[];
    uint32_t sbase = smem_u32(smem);

    const int tid = threadIdx.x;
    const int wid = tid >> 5;
    const int l   = tid & 31;
    const int wm  = wid >> 2;
    const int wn  = wid & 3;
    const int mo  = wm * (BM / 2);
    const int no  = wn * 32;

    const int rowBase = blockIdx.y * BM;
    const int colBase = blockIdx.x * 128;

    if (tid < 128) {
        float bv;
        if (EPI == 0)
            bv = (colBase < 2 * DINNER) ? biasA[colBase + tid]
                                        : biasB[colBase - 2 * DINNER + tid];
        else
            bv = biasA[colBase + tid];
        *reinterpret_cast<float*>(smem + BIASOF + tid * 4) = bv;
    }

    const uint32_t aRow = (uint32_t)((mo + (l & 15)) * ROWB + ((l >> 4) * 16));
    const uint32_t bRow = (uint32_t)((no + (l & 7) + ((l & 16) ? 8 : 0)) * ROWB
                                     + (((l >> 3) & 1) * 16));

    float acc[MI][4][4];
#pragma unroll
    for (int mi = 0; mi < MI; mi++)
#pragma unroll
        for (int ni = 0; ni < 4; ni++)
#pragma unroll
            for (int r = 0; r < 4; r++) acc[mi][ni][r] = 0.0f;

    const int NC = K / 32;

    {
        tile_cpasync<BM >(A, rowBase, 0, K, sbase,         tid);
        tile_cpasync<128>(W, colBase, 0, K, sbase + ATILE, tid);
        cpa_commit();
        tile_cpasync<BM >(A, rowBase, 32, K, sbase + STAGE,         tid);
        tile_cpasync<128>(W, colBase, 32, K, sbase + STAGE + ATILE, tid);
        cpa_commit();
    }

    for (int c = 0; c < NC; c++) {
        if (c + 2 < NC) {
            uint32_t st = sbase + ((c + 2) % 3) * STAGE;
            int kt = (c + 2) * 32;
            tile_cpasync<BM >(A, rowBase, kt, K, st,         tid);
            tile_cpasync<128>(W, colBase, kt, K, st + ATILE, tid);
            cpa_commit();
            cpa_wait<2>();
        } else if (c + 1 < NC) {
            cpa_wait<1>();
        } else {
            cpa_wait<0>();
        }
        __syncthreads();

        uint32_t st = sbase + (c % 3) * STAGE;
#pragma unroll
        for (int ks = 0; ks < 2; ks++) {
            uint32_t ah[MI][4], bh[8];
#pragma unroll
            for (int mi = 0; mi < MI; mi++) {
                uint32_t ad = st + aRow + mi * (16 * ROWB) + ks * 32;
                ldsm4(ah[mi][0], ah[mi][1], ah[mi][2], ah[mi][3], ad);
            }
#pragma unroll
            for (int np = 0; np < 2; np++) {
                uint32_t bd = st + ATILE + bRow + np * (16 * ROWB) + ks * 32;
                ldsm4(bh[np * 4 + 0], bh[np * 4 + 1], bh[np * 4 + 2], bh[np * 4 + 3], bd);
            }
#pragma unroll
            for (int mi = 0; mi < MI; mi++)
#pragma unroll
                for (int ni = 0; ni < 4; ni++)
                    mma16816(acc[mi][ni], ah[mi], &bh[ni * 2]);
        }
        __syncthreads();
    }

    const float* sb = reinterpret_cast<const float*>(smem + BIASOF);
    const int g  = l >> 2;
    const int t4 = l & 3;
#pragma unroll
    for (int mi = 0; mi < MI; mi++) {
#pragma unroll
        for (int ni = 0; ni < 4; ni++) {
            int bc   = no + ni * 8 + 2 * t4;
            int col  = colBase + bc;
            int row0 = rowBase + mo + mi * 16 + g;
            int row1 = row0 + 8;
            float2 v0, v1;
            v0.x = acc[mi][ni][0] + sb[bc];
            v0.y = acc[mi][ni][1] + sb[bc + 1];
            v1.x = acc[mi][ni][2] + sb[bc];
            v1.y = acc[mi][ni][3] + sb[bc + 1];
            if (EPI == 0) {
                if (colBase < DINNER) {
                    *reinterpret_cast<float2*>(&g_xproj[(size_t)row0 * DINNER + col]) = v0;
                    *reinterpret_cast<float2*>(&g_xproj[(size_t)row1 * DINNER + col]) = v1;
                } else if (colBase < 2 * DINNER) {
                    v0.x = fmaxf(v0.x, 0.f); v0.y = fmaxf(v0.y, 0.f);
                    v1.x = fmaxf(v1.x, 0.f); v1.y = fmaxf(v1.y, 0.f);
                    int cc = col - DINNER;
                    *reinterpret_cast<float2*>(&g_delta[(size_t)row0 * DINNER + cc]) = v0;
                    *reinterpret_cast<float2*>(&g_delta[(size_t)row1 * DINNER + cc]) = v1;
                } else {
                    v0.x = 1.f / (1.f + fexp(-v0.x));
                    v0.y = 1.f / (1.f + fexp(-v0.y));
                    v1.x = 1.f / (1.f + fexp(-v1.x));
                    v1.y = 1.f / (1.f + fexp(-v1.y));
                    int cc = col - 2 * DINNER;
                    *reinterpret_cast<float2*>(&g_gate[(size_t)row0 * DINNER + cc]) = v0;
                    *reinterpret_cast<float2*>(&g_gate[(size_t)row1 * DINNER + cc]) = v1;
                }
            } else {
                *reinterpret_cast<float2*>(&Cout[(size_t)row0 * N + col]) = v0;
                *reinterpret_cast<float2*>(&Cout[(size_t)row1 * N + col]) = v1;
            }
        }
    }
}

// ---------------------------------------------------------------------------
// Fused fp32 -> fp16 convert for all four source arrays (one launch)
// ---------------------------------------------------------------------------
#define CR0 (TOK * DMODEL / 8)
#define CR1 (2 * DINNER * DMODEL / 8)
#define CR2 (DINNER * DMODEL / 8)
#define CR3 (DMODEL * DINNER / 8)
#define CRT (CR0 + CR1 + CR2 + CR3)

__global__ void __launch_bounds__(256)
conv_all_kernel(const float4* __restrict__ sx, const float4* __restrict__ swi,
                const float4* __restrict__ swg, const float4* __restrict__ swo,
                uint4* __restrict__ dx, uint4* __restrict__ dwi,
                uint4* __restrict__ dwg, uint4* __restrict__ dwo)
{
    int i = blockIdx.x * blockDim.x + threadIdx.x;
    if (i >= CRT) return;
    const float4* s; uint4* d; int off;
    if (i < CR0)                   { s = sx;  d = dx;  off = i; }
    else if (i < CR0 + CR1)        { s = swi; d = dwi; off = i - CR0; }
    else if (i < CR0 + CR1 + CR2)  { s = swg; d = dwg; off = i - CR0 - CR1; }
    else                           { s = swo; d = dwo; off = i - CR0 - CR1 - CR2; }
    float4 u = s[2 * off];
    float4 v = s[2 * off + 1];
    __half2 h0 = __floats2half2_rn(u.x, u.y);
    __half2 h1 = __floats2half2_rn(u.z, u.w);
    __half2 h2 = __floats2half2_rn(v.x, v.y);
    __half2 h3 = __floats2half2_rn(v.z, v.w);
    uint4 o;
    o.x = *reinterpret_cast<uint32_t*>(&h0);
    o.y = *reinterpret_cast<uint32_t*>(&h1);
    o.z = *reinterpret_cast<uint32_t*>(&h2);
    o.w = *reinterpret_cast<uint32_t*>(&h3);
    d[off] = o;
}

// ---------------------------------------------------------------------------
// Chunked selective scan with SMEM-staged inputs.
// CTA = 16 channel-groups of one (chunk, 16-slot) tile; inputs staged once.
// Row stride 20 floats keeps the float4 staging STS conflict-free.
// ---------------------------------------------------------------------------
#define SROW 20

__global__ void __launch_bounds__(256)
scanA_kernel(const float* __restrict__ A_log, const float* __restrict__ B_mat)
{
    __shared__ float sdel[CHL][SROW];
    __shared__ float sxp [CHL][SROW];

    int tid   = threadIdx.x;
    int gidx0 = blockIdx.x * 16;
    int chunk = gidx0 >> 12;
    int slot0 = gidx0 & (NSLOT - 1);
    int b     = slot0 >> 11;
    int ch0   = slot0 & (DINNER - 1);

    size_t base = (size_t)(b * SEQLEN + chunk * CHL) * DINNER + ch0;

    // cooperative stage: 64 rows x 16 floats per array
    {
        int t  = tid >> 2;
        int c4 = (tid & 3) * 4;
        *reinterpret_cast<float4*>(&sdel[t][c4]) =
            *reinterpret_cast<const float4*>(&g_delta[base + (size_t)t * DINNER + c4]);
        *reinterpret_cast<float4*>(&sxp[t][c4]) =
            *reinterpret_cast<const float4*>(&g_xproj[base + (size_t)t * DINNER + c4]);
    }
    __syncthreads();

    int g = tid >> 4;
    int s = tid & 15;
    int ch = ch0 + g;

    float As = -__expf(A_log[ch * DSTATE + s]);
    float Bs = B_mat[ch * DSTATE + s];

    float P = 1.0f, q = 0.0f;
#pragma unroll 4
    for (int t = 0; t < CHL; t++) {
        float dt = sdel[t][g];
        float xt = sxp[t][g];
        float a  = __expf(As * dt);
        q = fmaf(q, a, (dt * xt) * Bs);
        P *= a;
    }
    size_t o = (size_t)(gidx0 + g) * DSTATE + s;
    g_P[o] = P;
    g_q[o] = q;
}

__global__ void __launch_bounds__(256)
scanB_kernel()
{
    int i = blockIdx.x * 256 + threadIdx.x;
    float P[CHK], q[CHK];
#pragma unroll
    for (int k = 0; k < CHK; k++) {
        P[k] = g_P[(size_t)k * NSS + i];
        q[k] = g_q[(size_t)k * NSS + i];
    }
    float h = 0.0f;
#pragma unroll
    for (int k = 0; k < CHK; k++) {
        g_h0[(size_t)k * NSS + i] = h;
        h = fmaf(P[k], h, q[k]);
    }
}

__global__ void __launch_bounds__(256)
scanC_kernel(const float* __restrict__ A_log, const float* __restrict__ B_mat,
             const float* __restrict__ C_mat, const float* __restrict__ D_vec)
{
    __shared__ float  sdel[CHL][SROW];
    __shared__ float  sxp [CHL][SROW];
    __shared__ float  sgt [CHL][SROW];
    __shared__ __half sout[CHL][16];

    int tid   = threadIdx.x;
    int gidx0 = blockIdx.x * 16;
    int chunk = gidx0 >> 12;
    int slot0 = gidx0 & (NSLOT - 1);
    int b     = slot0 >> 11;
    int ch0   = slot0 & (DINNER - 1);

    size_t base = (size_t)(b * SEQLEN + chunk * CHL) * DINNER + ch0;

    {
        int t  = tid >> 2;
        int c4 = (tid & 3) * 4;
        *reinterpret_cast<float4*>(&sdel[t][c4]) =
            *reinterpret_cast<const float4*>(&g_delta[base + (size_t)t * DINNER + c4]);
        *reinterpret_cast<float4*>(&sxp[t][c4]) =
            *reinterpret_cast<const float4*>(&g_xproj[base + (size_t)t * DINNER + c4]);
        *reinterpret_cast<float4*>(&sgt[t][c4]) =
            *reinterpret_cast<const float4*>(&g_gate[base + (size_t)t * DINNER + c4]);
    }
    __syncthreads();

    int g = tid >> 4;
    int s = tid & 15;
    int ch = ch0 + g;

    float As  = -__expf(A_log[ch * DSTATE + s]);
    float Bs  = B_mat[ch * DSTATE + s];
    float cs  = C_mat[s];
    float Dch = D_vec[ch];

    float h = g_h0[(size_t)(gidx0 + g) * DSTATE + s];

#pragma unroll 4
    for (int t = 0; t < CHL; t++) {
        float dt = sdel[t][g];
        float xt = sxp[t][g];
        float a  = __expf(As * dt);
        h = fmaf(h, a, (dt * xt) * Bs);
        float p = h * cs;
        p += __shfl_xor_sync(0xffffffffu, p, 1);
        p += __shfl_xor_sync(0xffffffffu, p, 2);
        p += __shfl_xor_sync(0xffffffffu, p, 4);
        p += __shfl_xor_sync(0xffffffffu, p, 8);
        if (s == 0) {
            float v = sgt[t][g] * (p + xt * Dch);
            sout[t][g] = __float2half(v);
        }
    }
    __syncthreads();

    // cooperative store: 64 rows x 16 halves (32B/row, coalesced)
    {
        int t  = tid >> 2;
        int c2 = (tid & 3) * 4;
        *reinterpret_cast<uint2*>(&g_gss[base + (size_t)t * DINNER + c2]) =
            *reinterpret_cast<const uint2*>(&sout[t][c2]);
    }
}

// ---------------------------------------------------------------------------
extern "C" void kernel_launch(void* const* d_in, const int* in_sizes, int n_in,
                              void* d_out, int out_size)
{
    const float* x      = (const float*)d_in[0];
    const float* W_in   = (const float*)d_in[1];
    const float* b_in   = (const float*)d_in[2];
    const float* W_gate = (const float*)d_in[3];
    const float* b_gate = (const float*)d_in[4];
    const float* W_out  = (const float*)d_in[5];
    const float* b_out  = (const float*)d_in[6];
    const float* A_log  = (const float*)d_in[7];
    const float* B_mat  = (const float*)d_in[8];
    const float* C_mat  = (const float*)d_in[9];
    const float* D_vec  = (const float*)d_in[10];
    float* out = (float*)d_out;

    cudaFuncSetAttribute((const void*)gemm_mma<0, 128>,
                         cudaFuncAttributeMaxDynamicSharedMemorySize, SMEMT(128));
    cudaFuncSetAttribute((const void*)gemm_mma<2, 64>,
                         cudaFuncAttributeMaxDynamicSharedMemorySize, SMEMT(64));

    __half *xh, *wi, *wo, *gs;
    cudaGetSymbolAddress((void**)&xh, g_x);
    cudaGetSymbolAddress((void**)&wi, g_wi);
    cudaGetSymbolAddress((void**)&wo, g_wo);
    cudaGetSymbolAddress((void**)&gs, g_gss);

    const size_t WG_OFF = (size_t)2 * DINNER * DMODEL;

    // 1) fused fp32 -> fp16 converts (single launch)
    conv_all_kernel<<<(CRT + 255) / 256, 256>>>(
        (const float4*)x, (const float4*)W_in, (const float4*)W_gate, (const float4*)W_out,
        (uint4*)xh, (uint4*)wi, (uint4*)(wi + WG_OFF), (uint4*)wo);

    // 2) fused in-proj + gate GEMM (N = 6144)
    gemm_mma<0, 128><<<dim3(NIN / 128, TOK / 128), 256, SMEMT(128)>>>(
        xh, wi, b_in, b_gate, nullptr, NIN, DMODEL);

    // 3) chunked selective scan (SMEM-staged)
    scanA_kernel<<<4096, 256>>>(A_log, B_mat);
    scanB_kernel<<<NSS / 256, 256>>>();
    scanC_kernel<<<4096, 256>>>(A_log, B_mat, C_mat, D_vec);

    // 4) out = gss @ W_out^T + b_out  (BM=64 -> 256 CTAs)
    gemm_mma<2, 64><<<dim3(DMODEL / 128, TOK / 64), 256, SMEMT(64)>>>(
        gs, wo, b_out, nullptr, out, DMODEL, DINNER);
}

// round 12
// speedup vs baseline: 1.7630x; 1.0385x over previous
#include <cuda_runtime.h>
#include <cuda_fp16.h>
#include <cstdint>

// Problem constants
#define TOK     2048
#define DMODEL  1024
#define DINNER  2048
#define DSTATE  16
#define SEQLEN  1024
#define NBATCH  2
#define NIN     (3 * DINNER)
#define CHK     16
#define CHL     (SEQLEN / CHK)
#define NSLOT   (NBATCH * DINNER)
#define NSS     (NSLOT * DSTATE)

#define LOG2E 1.4426950408889634f

// ---------------------------------------------------------------------------
// Device-global scratch
// ---------------------------------------------------------------------------
__device__ float g_xproj[TOK * DINNER];
__device__ float g_delta[TOK * DINNER];
__device__ float g_gate [TOK * DINNER];

__device__ float g_P[CHK * NSS];
__device__ float g_q[CHK * NSS];

__device__ __half g_x  [TOK * DMODEL];
__device__ __half g_wi [NIN * DMODEL];
__device__ __half g_wo [DMODEL * DINNER];
__device__ __half g_gss[TOK * DINNER];

// ---------------------------------------------------------------------------
// PTX helpers
// ---------------------------------------------------------------------------
__device__ __forceinline__ uint32_t smem_u32(const void* p) {
    uint32_t a;
    asm("{ .reg .u64 t; cvta.to.shared.u64 t, %1; cvt.u32.u64 %0, t; }" : "=r"(a) : "l"(p));
    return a;
}
__device__ __forceinline__ void cpa16(uint32_t s, const void* g) {
    asm volatile("cp.async.cg.shared.global [%0], [%1], 16;" :: "r"(s), "l"(g) : "memory");
}
__device__ __forceinline__ void cpa_commit() {
    asm volatile("cp.async.commit_group;" ::: "memory");
}
template <int N>
__device__ __forceinline__ void cpa_wait() {
    asm volatile("cp.async.wait_group %0;" :: "n"(N) : "memory");
}
__device__ __forceinline__ void ldsm4(uint32_t& r0, uint32_t& r1, uint32_t& r2,
                                      uint32_t& r3, uint32_t a) {
    asm volatile("ldmatrix.sync.aligned.m8n8.x4.shared.b16 {%0,%1,%2,%3}, [%4];"
                 : "=r"(r0), "=r"(r1), "=r"(r2), "=r"(r3) : "r"(a));
}
__device__ __forceinline__ void mma16816(float* d, const uint32_t* a, const uint32_t* b) {
    asm volatile(
        "mma.sync.aligned.m16n8k16.row.col.f32.f16.f16.f32 "
        "{%0,%1,%2,%3}, {%4,%5,%6,%7}, {%8,%9}, {%0,%1,%2,%3};"
        : "+f"(d[0]), "+f"(d[1]), "+f"(d[2]), "+f"(d[3])
        : "r"(a[0]), "r"(a[1]), "r"(a[2]), "r"(a[3]), "r"(b[0]), "r"(b[1]));
}

// Fast exp on FMA/ALU pipes (GEMM epilogue sigmoid only)
__device__ __forceinline__ float fexp(float z) {
    float nf = rintf(z * LOG2E);
    float r  = fmaf(nf, -0.693145751953125f, z);
    r        = fmaf(nf, -1.42860677e-6f, r);
    float p  = 1.0f / 720.0f;
    p = fmaf(p, r, 1.0f / 120.0f);
    p = fmaf(p, r, 1.0f / 24.0f);
    p = fmaf(p, r, 1.0f / 6.0f);
    p = fmaf(p, r, 0.5f);
    p = fmaf(p, r, 1.0f);
    p = fmaf(p, r, 1.0f);
    float s = __int_as_float(((int)nf + 127) << 23);
    return p * s;
}

// ---------------------------------------------------------------------------
// SMEM: stage = A (BM rows) ++ W (128 rows), 80B rows, TRIPLE buffered
// ---------------------------------------------------------------------------
#define ROWB 80
#define SMEMT(BM) (3 * ((BM) * ROWB + 128 * ROWB) + 512)

template <int ROWS>
__device__ __forceinline__ void tile_cpasync(const __half* __restrict__ g,
                                             int rowBase, int kt, int ld,
                                             uint32_t sdst, int tid) {
#pragma unroll
    for (int i = 0; i < ROWS / 64; i++) {
        int seg = tid + i * 256;
        int r   = seg >> 2;
        int c   = seg & 3;
        cpa16(sdst + r * ROWB + c * 16,
              g + (size_t)(rowBase + r) * ld + kt + c * 8);
    }
}

// ---------------------------------------------------------------------------
// fp16 GEMM: C = A @ W^T + bias ; 3-stage cp.async pipeline, 1 sync/iter
// ---------------------------------------------------------------------------
template <int EPI, int BM>
__global__ void __launch_bounds__(256, 2)
gemm_mma(const __half* __restrict__ A, const __half* __restrict__ W,
         const float* __restrict__ biasA, const float* __restrict__ biasB,
         float* __restrict__ Cout, int N, int K)
{
    constexpr int MI     = BM / 32;
    constexpr int ATILE  = BM * ROWB;
    constexpr int BTILE  = 128 * ROWB;
    constexpr int STAGE  = ATILE + BTILE;
    constexpr int BIASOF = 3 * STAGE;

    extern __shared__ char smem[];
    uint32_t sbase = smem_u32(smem);

    const int tid = threadIdx.x;
    const int wid = tid >> 5;
    const int l   = tid & 31;
    const int wm  = wid >> 2;
    const int wn  = wid & 3;
    const int mo  = wm * (BM / 2);
    const int no  = wn * 32;

    const int rowBase = blockIdx.y * BM;
    const int colBase = blockIdx.x * 128;

    if (tid < 128) {
        float bv;
        if (EPI == 0)
            bv = (colBase < 2 * DINNER) ? biasA[colBase + tid]
                                        : biasB[colBase - 2 * DINNER + tid];
        else
            bv = biasA[colBase + tid];
        *reinterpret_cast<float*>(smem + BIASOF + tid * 4) = bv;
    }

    const uint32_t aRow = (uint32_t)((mo + (l & 15)) * ROWB + ((l >> 4) * 16));
    const uint32_t bRow = (uint32_t)((no + (l & 7) + ((l & 16) ? 8 : 0)) * ROWB
                                     + (((l >> 3) & 1) * 16));

    float acc[MI][4][4];
#pragma unroll
    for (int mi = 0; mi < MI; mi++)
#pragma unroll
        for (int ni = 0; ni < 4; ni++)
#pragma unroll
            for (int r = 0; r < 4; r++) acc[mi][ni][r] = 0.0f;

    const int NC = K / 32;

    // prologue: chunks 0,1 into stages 0,1
    {
        tile_cpasync<BM >(A, rowBase, 0, K, sbase,         tid);
        tile_cpasync<128>(W, colBase, 0, K, sbase + ATILE, tid);
        cpa_commit();
        tile_cpasync<BM >(A, rowBase, 32, K, sbase + STAGE,         tid);
        tile_cpasync<128>(W, colBase, 32, K, sbase + STAGE + ATILE, tid);
        cpa_commit();
    }

    for (int c = 0; c < NC; c++) {
        // ensure stage c arrived
        if (c + 1 < NC) cpa_wait<1>();
        else            cpa_wait<0>();
        __syncthreads();   // also guarantees stage (c-1)%3 fully consumed

        // prefetch chunk c+2 into stage (c+2)%3 == (c-1)%3 (safe after sync)
        if (c + 2 < NC) {
            uint32_t st = sbase + ((c + 2) % 3) * STAGE;
            int kt = (c + 2) * 32;
            tile_cpasync<BM >(A, rowBase, kt, K, st,         tid);
            tile_cpasync<128>(W, colBase, kt, K, st + ATILE, tid);
            cpa_commit();
        }

        uint32_t st = sbase + (c % 3) * STAGE;
#pragma unroll
        for (int ks = 0; ks < 2; ks++) {
            uint32_t ah[MI][4], bh[8];
#pragma unroll
            for (int mi = 0; mi < MI; mi++) {
                uint32_t ad = st + aRow + mi * (16 * ROWB) + ks * 32;
                ldsm4(ah[mi][0], ah[mi][1], ah[mi][2], ah[mi][3], ad);
            }
#pragma unroll
            for (int np = 0; np < 2; np++) {
                uint32_t bd = st + ATILE + bRow + np * (16 * ROWB) + ks * 32;
                ldsm4(bh[np * 4 + 0], bh[np * 4 + 1], bh[np * 4 + 2], bh[np * 4 + 3], bd);
            }
#pragma unroll
            for (int mi = 0; mi < MI; mi++)
#pragma unroll
                for (int ni = 0; ni < 4; ni++)
                    mma16816(acc[mi][ni], ah[mi], &bh[ni * 2]);
        }
    }

    __syncthreads();
    const float* sb = reinterpret_cast<const float*>(smem + BIASOF);
    const int g  = l >> 2;
    const int t4 = l & 3;
#pragma unroll
    for (int mi = 0; mi < MI; mi++) {
#pragma unroll
        for (int ni = 0; ni < 4; ni++) {
            int bc   = no + ni * 8 + 2 * t4;
            int col  = colBase + bc;
            int row0 = rowBase + mo + mi * 16 + g;
            int row1 = row0 + 8;
            float2 v0, v1;
            v0.x = acc[mi][ni][0] + sb[bc];
            v0.y = acc[mi][ni][1] + sb[bc + 1];
            v1.x = acc[mi][ni][2] + sb[bc];
            v1.y = acc[mi][ni][3] + sb[bc + 1];
            if (EPI == 0) {
                if (colBase < DINNER) {
                    *reinterpret_cast<float2*>(&g_xproj[(size_t)row0 * DINNER + col]) = v0;
                    *reinterpret_cast<float2*>(&g_xproj[(size_t)row1 * DINNER + col]) = v1;
                } else if (colBase < 2 * DINNER) {
                    v0.x = fmaxf(v0.x, 0.f); v0.y = fmaxf(v0.y, 0.f);
                    v1.x = fmaxf(v1.x, 0.f); v1.y = fmaxf(v1.y, 0.f);
                    int cc = col - DINNER;
                    *reinterpret_cast<float2*>(&g_delta[(size_t)row0 * DINNER + cc]) = v0;
                    *reinterpret_cast<float2*>(&g_delta[(size_t)row1 * DINNER + cc]) = v1;
                } else {
                    v0.x = 1.f / (1.f + fexp(-v0.x));
                    v0.y = 1.f / (1.f + fexp(-v0.y));
                    v1.x = 1.f / (1.f + fexp(-v1.x));
                    v1.y = 1.f / (1.f + fexp(-v1.y));
                    int cc = col - 2 * DINNER;
                    *reinterpret_cast<float2*>(&g_gate[(size_t)row0 * DINNER + cc]) = v0;
                    *reinterpret_cast<float2*>(&g_gate[(size_t)row1 * DINNER + cc]) = v1;
                }
            } else {
                *reinterpret_cast<float2*>(&Cout[(size_t)row0 * N + col]) = v0;
                *reinterpret_cast<float2*>(&Cout[(size_t)row1 * N + col]) = v1;
            }
        }
    }
}

// ---------------------------------------------------------------------------
// Fused fp32 -> fp16 convert for all four source arrays (one launch)
// ---------------------------------------------------------------------------
#define CR0 (TOK * DMODEL / 8)
#define CR1 (2 * DINNER * DMODEL / 8)
#define CR2 (DINNER * DMODEL / 8)
#define CR3 (DMODEL * DINNER / 8)
#define CRT (CR0 + CR1 + CR2 + CR3)

__global__ void __launch_bounds__(256)
conv_all_kernel(const float4* __restrict__ sx, const float4* __restrict__ swi,
                const float4* __restrict__ swg, const float4* __restrict__ swo,
                uint4* __restrict__ dx, uint4* __restrict__ dwi,
                uint4* __restrict__ dwg, uint4* __restrict__ dwo)
{
    int i = blockIdx.x * blockDim.x + threadIdx.x;
    if (i >= CRT) return;
    const float4* s; uint4* d; int off;
    if (i < CR0)                   { s = sx;  d = dx;  off = i; }
    else if (i < CR0 + CR1)        { s = swi; d = dwi; off = i - CR0; }
    else if (i < CR0 + CR1 + CR2)  { s = swg; d = dwg; off = i - CR0 - CR1; }
    else                           { s = swo; d = dwo; off = i - CR0 - CR1 - CR2; }
    float4 u = s[2 * off];
    float4 v = s[2 * off + 1];
    __half2 h0 = __floats2half2_rn(u.x, u.y);
    __half2 h1 = __floats2half2_rn(u.z, u.w);
    __half2 h2 = __floats2half2_rn(v.x, v.y);
    __half2 h3 = __floats2half2_rn(v.z, v.w);
    uint4 o;
    o.x = *reinterpret_cast<uint32_t*>(&h0);
    o.y = *reinterpret_cast<uint32_t*>(&h1);
    o.z = *reinterpret_cast<uint32_t*>(&h2);
    o.w = *reinterpret_cast<uint32_t*>(&h3);
    d[off] = o;
}

// ---------------------------------------------------------------------------
// Chunked selective scan, SMEM-staged inputs, exp2-form decay.
// scanA: per-chunk (P,q).  scanC: self-composed h0 + replay + gate.
// ---------------------------------------------------------------------------
#define SROW 20

__global__ void __launch_bounds__(256)
scanA_kernel(const float* __restrict__ A_log, const float* __restrict__ B_mat)
{
    __shared__ float sdel[CHL][SROW];
    __shared__ float sxp [CHL][SROW];

    int tid   = threadIdx.x;
    int gidx0 = blockIdx.x * 16;
    int chunk = gidx0 >> 12;
    int slot0 = gidx0 & (NSLOT - 1);
    int b     = slot0 >> 11;
    int ch0   = slot0 & (DINNER - 1);

    size_t base = (size_t)(b * SEQLEN + chunk * CHL) * DINNER + ch0;

    {
        int t  = tid >> 2;
        int c4 = (tid & 3) * 4;
        *reinterpret_cast<float4*>(&sdel[t][c4]) =
            *reinterpret_cast<const float4*>(&g_delta[base + (size_t)t * DINNER + c4]);
        *reinterpret_cast<float4*>(&sxp[t][c4]) =
            *reinterpret_cast<const float4*>(&g_xproj[base + (size_t)t * DINNER + c4]);
    }
    __syncthreads();

    int g = tid >> 4;
    int s = tid & 15;
    int ch = ch0 + g;

    float As2 = -__expf(A_log[ch * DSTATE + s]) * LOG2E;   // pre-scaled for exp2
    float Bs  = B_mat[ch * DSTATE + s];

    float P = 1.0f, q = 0.0f;
#pragma unroll 4
    for (int t = 0; t < CHL; t++) {
        float dt = sdel[t][g];
        float xt = sxp[t][g];
        float a  = exp2f(As2 * dt);
        q = fmaf(q, a, (dt * xt) * Bs);
        P *= a;
    }
    size_t o = (size_t)(gidx0 + g) * DSTATE + s;
    g_P[o] = P;
    g_q[o] = q;
}

__global__ void __launch_bounds__(256)
scanC_kernel(const float* __restrict__ A_log, const float* __restrict__ B_mat,
             const float* __restrict__ C_mat, const float* __restrict__ D_vec)
{
    __shared__ float  sdel[CHL][SROW];
    __shared__ float  sxp [CHL][SROW];
    __shared__ float  sgt [CHL][SROW];
    __shared__ __half sout[CHL][16];

    int tid   = threadIdx.x;
    int gidx0 = blockIdx.x * 16;
    int chunk = gidx0 >> 12;
    int slot0 = gidx0 & (NSLOT - 1);
    int b     = slot0 >> 11;
    int ch0   = slot0 & (DINNER - 1);

    size_t base = (size_t)(b * SEQLEN + chunk * CHL) * DINNER + ch0;

    {
        int t  = tid >> 2;
        int c4 = (tid & 3) * 4;
        *reinterpret_cast<float4*>(&sdel[t][c4]) =
            *reinterpret_cast<const float4*>(&g_delta[base + (size_t)t * DINNER + c4]);
        *reinterpret_cast<float4*>(&sxp[t][c4]) =
            *reinterpret_cast<const float4*>(&g_xproj[base + (size_t)t * DINNER + c4]);
        *reinterpret_cast<float4*>(&sgt[t][c4]) =
            *reinterpret_cast<const float4*>(&g_gate[base + (size_t)t * DINNER + c4]);
    }

    int g = tid >> 4;
    int s = tid & 15;
    int ch = ch0 + g;
    int slot = slot0 + g;

    float As2 = -__expf(A_log[ch * DSTATE + s]) * LOG2E;
    float Bs  = B_mat[ch * DSTATE + s];
    float cs  = C_mat[s];
    float Dch = D_vec[ch];

    // self-compose h0 from per-chunk (P,q): batched predicated loads + fma chain
    float Pr[CHK], qr[CHK];
#pragma unroll
    for (int j = 0; j < CHK; j++) {
        bool v = (j < chunk);
        size_t o = ((size_t)(j << 12) + slot) * DSTATE + s;
        Pr[j] = v ? g_P[o] : 1.0f;
        qr[j] = v ? g_q[o] : 0.0f;
    }
    float h = 0.0f;
#pragma unroll
    for (int j = 0; j < CHK; j++) h = fmaf(Pr[j], h, qr[j]);

    __syncthreads();

#pragma unroll 4
    for (int t = 0; t < CHL; t++) {
        float dt = sdel[t][g];
        float xt = sxp[t][g];
        float a  = exp2f(As2 * dt);
        h = fmaf(h, a, (dt * xt) * Bs);
        float p = h * cs;
        p += __shfl_xor_sync(0xffffffffu, p, 1);
        p += __shfl_xor_sync(0xffffffffu, p, 2);
        p += __shfl_xor_sync(0xffffffffu, p, 4);
        p += __shfl_xor_sync(0xffffffffu, p, 8);
        if (s == 0) {
            float v = sgt[t][g] * (p + xt * Dch);
            sout[t][g] = __float2half(v);
        }
    }
    __syncthreads();

    {
        int t  = tid >> 2;
        int c2 = (tid & 3) * 4;
        *reinterpret_cast<uint2*>(&g_gss[base + (size_t)t * DINNER + c2]) =
            *reinterpret_cast<const uint2*>(&sout[t][c2]);
    }
}

// ---------------------------------------------------------------------------
extern "C" void kernel_launch(void* const* d_in, const int* in_sizes, int n_in,
                              void* d_out, int out_size)
{
    const float* x      = (const float*)d_in[0];
    const float* W_in   = (const float*)d_in[1];
    const float* b_in   = (const float*)d_in[2];
    const float* W_gate = (const float*)d_in[3];
    const float* b_gate = (const float*)d_in[4];
    const float* W_out  = (const float*)d_in[5];
    const float* b_out  = (const float*)d_in[6];
    const float* A_log  = (const float*)d_in[7];
    const float* B_mat  = (const float*)d_in[8];
    const float* C_mat  = (const float*)d_in[9];
    const float* D_vec  = (const float*)d_in[10];
    float* out = (float*)d_out;

    cudaFuncSetAttribute((const void*)gemm_mma<0, 128>,
                         cudaFuncAttributeMaxDynamicSharedMemorySize, SMEMT(128));
    cudaFuncSetAttribute((const void*)gemm_mma<2, 64>,
                         cudaFuncAttributeMaxDynamicSharedMemorySize, SMEMT(64));

    __half *xh, *wi, *wo, *gs;
    cudaGetSymbolAddress((void**)&xh, g_x);
    cudaGetSymbolAddress((void**)&wi, g_wi);
    cudaGetSymbolAddress((void**)&wo, g_wo);
    cudaGetSymbolAddress((void**)&gs, g_gss);

    const size_t WG_OFF = (size_t)2 * DINNER * DMODEL;

    // 1) fused fp32 -> fp16 converts
    conv_all_kernel<<<(CRT + 255) / 256, 256>>>(
        (const float4*)x, (const float4*)W_in, (const float4*)W_gate, (const float4*)W_out,
        (uint4*)xh, (uint4*)wi, (uint4*)(wi + WG_OFF), (uint4*)wo);

    // 2) fused in-proj + gate GEMM (N = 6144)
    gemm_mma<0, 128><<<dim3(NIN / 128, TOK / 128), 256, SMEMT(128)>>>(
        xh, wi, b_in, b_gate, nullptr, NIN, DMODEL);

    // 3) chunked selective scan (scanB folded into scanC)
    scanA_kernel<<<4096, 256>>>(A_log, B_mat);
    scanC_kernel<<<4096, 256>>>(A_log, B_mat, C_mat, D_vec);

    // 4) out = gss @ W_out^T + b_out  (BM=64 -> 256 CTAs)
    gemm_mma<2, 64><<<dim3(DMODEL / 128, TOK / 64), 256, SMEMT(64)>>>(
        gs, wo, b_out, nullptr, out, DMODEL, DINNER);
}

// round 14
// speedup vs baseline: 2.0988x; 1.1905x over previous
#include <cuda_runtime.h>
#include <cuda_fp16.h>
#include <cstdint>

// Problem constants
#define TOK     2048
#define DMODEL  1024
#define DINNER  2048
#define DSTATE  16
#define SEQLEN  1024
#define NBATCH  2
#define NIN     (3 * DINNER)
#define CHK     16
#define CHL     (SEQLEN / CHK)
#define NSLOT   (NBATCH * DINNER)
#define NSS     (NSLOT * DSTATE)

#define LOG2E 1.4426950408889634f

// ---------------------------------------------------------------------------
// Device-global scratch
// ---------------------------------------------------------------------------
__device__ float g_xproj[TOK * DINNER];
__device__ float g_delta[TOK * DINNER];
__device__ float g_gate [TOK * DINNER];

__device__ float g_P[CHK * NSS];
__device__ float g_q[CHK * NSS];

__device__ __half g_x  [TOK * DMODEL];
__device__ __half g_wi [NIN * DMODEL];
__device__ __half g_wo [DMODEL * DINNER];
__device__ __half g_gss[TOK * DINNER];

// ---------------------------------------------------------------------------
// PTX helpers
// ---------------------------------------------------------------------------
__device__ __forceinline__ uint32_t smem_u32(const void* p) {
    uint32_t a;
    asm("{ .reg .u64 t; cvta.to.shared.u64 t, %1; cvt.u32.u64 %0, t; }" : "=r"(a) : "l"(p));
    return a;
}
__device__ __forceinline__ void cpa16(uint32_t s, const void* g) {
    asm volatile("cp.async.cg.shared.global [%0], [%1], 16;" :: "r"(s), "l"(g) : "memory");
}
__device__ __forceinline__ void cpa_commit() {
    asm volatile("cp.async.commit_group;" ::: "memory");
}
template <int N>
__device__ __forceinline__ void cpa_wait() {
    asm volatile("cp.async.wait_group %0;" :: "n"(N) : "memory");
}
__device__ __forceinline__ void ldsm4(uint32_t& r0, uint32_t& r1, uint32_t& r2,
                                      uint32_t& r3, uint32_t a) {
    asm volatile("ldmatrix.sync.aligned.m8n8.x4.shared.b16 {%0,%1,%2,%3}, [%4];"
                 : "=r"(r0), "=r"(r1), "=r"(r2), "=r"(r3) : "r"(a));
}
__device__ __forceinline__ void mma16816(float* d, const uint32_t* a, const uint32_t* b) {
    asm volatile(
        "mma.sync.aligned.m16n8k16.row.col.f32.f16.f16.f32 "
        "{%0,%1,%2,%3}, {%4,%5,%6,%7}, {%8,%9}, {%0,%1,%2,%3};"
        : "+f"(d[0]), "+f"(d[1]), "+f"(d[2]), "+f"(d[3])
        : "r"(a[0]), "r"(a[1]), "r"(a[2]), "r"(a[3]), "r"(b[0]), "r"(b[1]));
}

// Fast exp on FMA/ALU pipes (GEMM epilogue sigmoid only)
__device__ __forceinline__ float fexp(float z) {
    float nf = rintf(z * LOG2E);
    float r  = fmaf(nf, -0.693145751953125f, z);
    r        = fmaf(nf, -1.42860677e-6f, r);
    float p  = 1.0f / 720.0f;
    p = fmaf(p, r, 1.0f / 120.0f);
    p = fmaf(p, r, 1.0f / 24.0f);
    p = fmaf(p, r, 1.0f / 6.0f);
    p = fmaf(p, r, 0.5f);
    p = fmaf(p, r, 1.0f);
    p = fmaf(p, r, 1.0f);
    float s = __int_as_float(((int)nf + 127) << 23);
    return p * s;
}

// ---------------------------------------------------------------------------
// GEMM SMEM: stage = A (BM rows) ++ W (128 rows), 80B rows, TRIPLE buffered
// ---------------------------------------------------------------------------
#define ROWB 80
#define SMEMT(BM) (3 * ((BM) * ROWB + 128 * ROWB) + 512)

template <int ROWS>
__device__ __forceinline__ void tile_cpasync(const __half* __restrict__ g,
                                             int rowBase, int kt, int ld,
                                             uint32_t sdst, int tid) {
#pragma unroll
    for (int i = 0; i < ROWS / 64; i++) {
        int seg = tid + i * 256;
        int r   = seg >> 2;
        int c   = seg & 3;
        cpa16(sdst + r * ROWB + c * 16,
              g + (size_t)(rowBase + r) * ld + kt + c * 8);
    }
}

// ---------------------------------------------------------------------------
// fp16 GEMM: C = A @ W^T + bias ; 3-stage cp.async pipeline, 1 sync/iter
// ---------------------------------------------------------------------------
template <int EPI, int BM>
__global__ void __launch_bounds__(256, 2)
gemm_mma(const __half* __restrict__ A, const __half* __restrict__ W,
         const float* __restrict__ biasA, const float* __restrict__ biasB,
         float* __restrict__ Cout, int N, int K)
{
    constexpr int MI     = BM / 32;
    constexpr int ATILE  = BM * ROWB;
    constexpr int BTILE  = 128 * ROWB;
    constexpr int STAGE  = ATILE + BTILE;
    constexpr int BIASOF = 3 * STAGE;

    extern __shared__ char smem[];
    uint32_t sbase = smem_u32(smem);

    const int tid = threadIdx.x;
    const int wid = tid >> 5;
    const int l   = tid & 31;
    const int wm  = wid >> 2;
    const int wn  = wid & 3;
    const int mo  = wm * (BM / 2);
    const int no  = wn * 32;

    const int rowBase = blockIdx.y * BM;
    const int colBase = blockIdx.x * 128;

    if (tid < 128) {
        float bv;
        if (EPI == 0)
            bv = (colBase < 2 * DINNER) ? biasA[colBase + tid]
                                        : biasB[colBase - 2 * DINNER + tid];
        else
            bv = biasA[colBase + tid];
        *reinterpret_cast<float*>(smem + BIASOF + tid * 4) = bv;
    }

    const uint32_t aRow = (uint32_t)((mo + (l & 15)) * ROWB + ((l >> 4) * 16));
    const uint32_t bRow = (uint32_t)((no + (l & 7) + ((l & 16) ? 8 : 0)) * ROWB
                                     + (((l >> 3) & 1) * 16));

    float acc[MI][4][4];
#pragma unroll
    for (int mi = 0; mi < MI; mi++)
#pragma unroll
        for (int ni = 0; ni < 4; ni++)
#pragma unroll
            for (int r = 0; r < 4; r++) acc[mi][ni][r] = 0.0f;

    const int NC = K / 32;

    {
        tile_cpasync<BM >(A, rowBase, 0, K, sbase,         tid);
        tile_cpasync<128>(W, colBase, 0, K, sbase + ATILE, tid);
        cpa_commit();
        tile_cpasync<BM >(A, rowBase, 32, K, sbase + STAGE,         tid);
        tile_cpasync<128>(W, colBase, 32, K, sbase + STAGE + ATILE, tid);
        cpa_commit();
    }

    for (int c = 0; c < NC; c++) {
        if (c + 1 < NC) cpa_wait<1>();
        else            cpa_wait<0>();
        __syncthreads();

        if (c + 2 < NC) {
            uint32_t st = sbase + ((c + 2) % 3) * STAGE;
            int kt = (c + 2) * 32;
            tile_cpasync<BM >(A, rowBase, kt, K, st,         tid);
            tile_cpasync<128>(W, colBase, kt, K, st + ATILE, tid);
            cpa_commit();
        }

        uint32_t st = sbase + (c % 3) * STAGE;
#pragma unroll
        for (int ks = 0; ks < 2; ks++) {
            uint32_t ah[MI][4], bh[8];
#pragma unroll
            for (int mi = 0; mi < MI; mi++) {
                uint32_t ad = st + aRow + mi * (16 * ROWB) + ks * 32;
                ldsm4(ah[mi][0], ah[mi][1], ah[mi][2], ah[mi][3], ad);
            }
#pragma unroll
            for (int np = 0; np < 2; np++) {
                uint32_t bd = st + ATILE + bRow + np * (16 * ROWB) + ks * 32;
                ldsm4(bh[np * 4 + 0], bh[np * 4 + 1], bh[np * 4 + 2], bh[np * 4 + 3], bd);
            }
#pragma unroll
            for (int mi = 0; mi < MI; mi++)
#pragma unroll
                for (int ni = 0; ni < 4; ni++)
                    mma16816(acc[mi][ni], ah[mi], &bh[ni * 2]);
        }
    }

    __syncthreads();
    const float* sb = reinterpret_cast<const float*>(smem + BIASOF);
    const int g  = l >> 2;
    const int t4 = l & 3;
#pragma unroll
    for (int mi = 0; mi < MI; mi++) {
#pragma unroll
        for (int ni = 0; ni < 4; ni++) {
            int bc   = no + ni * 8 + 2 * t4;
            int col  = colBase + bc;
            int row0 = rowBase + mo + mi * 16 + g;
            int row1 = row0 + 8;
            float2 v0, v1;
            v0.x = acc[mi][ni][0] + sb[bc];
            v0.y = acc[mi][ni][1] + sb[bc + 1];
            v1.x = acc[mi][ni][2] + sb[bc];
            v1.y = acc[mi][ni][3] + sb[bc + 1];
            if (EPI == 0) {
                if (colBase < DINNER) {
                    *reinterpret_cast<float2*>(&g_xproj[(size_t)row0 * DINNER + col]) = v0;
                    *reinterpret_cast<float2*>(&g_xproj[(size_t)row1 * DINNER + col]) = v1;
                } else if (colBase < 2 * DINNER) {
                    v0.x = fmaxf(v0.x, 0.f); v0.y = fmaxf(v0.y, 0.f);
                    v1.x = fmaxf(v1.x, 0.f); v1.y = fmaxf(v1.y, 0.f);
                    int cc = col - DINNER;
                    *reinterpret_cast<float2*>(&g_delta[(size_t)row0 * DINNER + cc]) = v0;
                    *reinterpret_cast<float2*>(&g_delta[(size_t)row1 * DINNER + cc]) = v1;
                } else {
                    v0.x = 1.f / (1.f + fexp(-v0.x));
                    v0.y = 1.f / (1.f + fexp(-v0.y));
                    v1.x = 1.f / (1.f + fexp(-v1.x));
                    v1.y = 1.f / (1.f + fexp(-v1.y));
                    int cc = col - 2 * DINNER;
                    *reinterpret_cast<float2*>(&g_gate[(size_t)row0 * DINNER + cc]) = v0;
                    *reinterpret_cast<float2*>(&g_gate[(size_t)row1 * DINNER + cc]) = v1;
                }
            } else {
                *reinterpret_cast<float2*>(&Cout[(size_t)row0 * N + col]) = v0;
                *reinterpret_cast<float2*>(&Cout[(size_t)row1 * N + col]) = v1;
            }
        }
    }
}

// ---------------------------------------------------------------------------
// Fused fp32 -> fp16 convert for all four source arrays (one launch)
// ---------------------------------------------------------------------------
#define CR0 (TOK * DMODEL / 8)
#define CR1 (2 * DINNER * DMODEL / 8)
#define CR2 (DINNER * DMODEL / 8)
#define CR3 (DMODEL * DINNER / 8)
#define CRT (CR0 + CR1 + CR2 + CR3)

__global__ void __launch_bounds__(256)
conv_all_kernel(const float4* __restrict__ sx, const float4* __restrict__ swi,
                const float4* __restrict__ swg, const float4* __restrict__ swo,
                uint4* __restrict__ dx, uint4* __restrict__ dwi,
                uint4* __restrict__ dwg, uint4* __restrict__ dwo)
{
    int i = blockIdx.x * blockDim.x + threadIdx.x;
    if (i >= CRT) return;
    const float4* s; uint4* d; int off;
    if (i < CR0)                   { s = sx;  d = dx;  off = i; }
    else if (i < CR0 + CR1)        { s = swi; d = dwi; off = i - CR0; }
    else if (i < CR0 + CR1 + CR2)  { s = swg; d = dwg; off = i - CR0 - CR1; }
    else                           { s = swo; d = dwo; off = i - CR0 - CR1 - CR2; }
    float4 u = s[2 * off];
    float4 v = s[2 * off + 1];
    __half2 h0 = __floats2half2_rn(u.x, u.y);
    __half2 h1 = __floats2half2_rn(u.z, u.w);
    __half2 h2 = __floats2half2_rn(v.x, v.y);
    __half2 h3 = __floats2half2_rn(v.z, v.w);
    uint4 o;
    o.x = *reinterpret_cast<uint32_t*>(&h0);
    o.y = *reinterpret_cast<uint32_t*>(&h1);
    o.z = *reinterpret_cast<uint32_t*>(&h2);
    o.w = *reinterpret_cast<uint32_t*>(&h3);
    d[off] = o;
}

// ---------------------------------------------------------------------------
// Chunked selective scan, 4 states per lane (channel = 4 lanes, warp = 8 ch,
// CTA = 64 channels x one chunk), SMEM-staged inputs.
// ---------------------------------------------------------------------------
#define SCW  64                 // channels per scan CTA
#define SPAD 68                 // row stride (floats)

__global__ void __launch_bounds__(256)
scanA_kernel(const float* __restrict__ A_log, const float* __restrict__ B_mat)
{
    __shared__ float sdel[CHL][SPAD];
    __shared__ float sxp [CHL][SPAD];

    int tid   = threadIdx.x;
    int gidx0 = blockIdx.x * SCW;            // (chunk<<12) + slot0
    int chunk = gidx0 >> 12;
    int slot0 = gidx0 & (NSLOT - 1);
    int b     = slot0 >> 11;
    int ch0   = slot0 & (DINNER - 1);

    size_t base = (size_t)(b * SEQLEN + chunk * CHL) * DINNER + ch0;

    // stage 64 t-rows x 64 channels
#pragma unroll
    for (int it = 0; it < 4; it++) {
        int t  = (tid >> 4) + it * 16;
        int c4 = (tid & 15) * 4;
        *reinterpret_cast<float4*>(&sdel[t][c4]) =
            *reinterpret_cast<const float4*>(&g_delta[base + (size_t)t * DINNER + c4]);
        *reinterpret_cast<float4*>(&sxp[t][c4]) =
            *reinterpret_cast<const float4*>(&g_xproj[base + (size_t)t * DINNER + c4]);
    }
    __syncthreads();

    int grp = tid >> 2;          // channel within tile (0..63)
    int s2  = tid & 3;           // state quad
    int ch  = ch0 + grp;

    float As2[4], Bs[4];
#pragma unroll
    for (int j = 0; j < 4; j++) {
        int s = s2 * 4 + j;
        As2[j] = -__expf(A_log[ch * DSTATE + s]) * LOG2E;
        Bs[j]  = B_mat[ch * DSTATE + s];
    }

    float P[4] = {1.f, 1.f, 1.f, 1.f};
    float q[4] = {0.f, 0.f, 0.f, 0.f};
#pragma unroll 4
    for (int t = 0; t < CHL; t++) {
        float dt = sdel[t][grp];
        float xt = sxp[t][grp];
        float u  = dt * xt;
#pragma unroll
        for (int j = 0; j < 4; j++) {
            float a = exp2f(As2[j] * dt);
            q[j] = fmaf(q[j], a, u * Bs[j]);
            P[j] *= a;
        }
    }
    size_t o = (size_t)(gidx0 + grp) * DSTATE + s2 * 4;
    *reinterpret_cast<float4*>(&g_P[o]) = make_float4(P[0], P[1], P[2], P[3]);
    *reinterpret_cast<float4*>(&g_q[o]) = make_float4(q[0], q[1], q[2], q[3]);
}

__global__ void __launch_bounds__(256)
scanC_kernel(const float* __restrict__ A_log, const float* __restrict__ B_mat,
             const float* __restrict__ C_mat, const float* __restrict__ D_vec)
{
    extern __shared__ char dsm[];
    float (*sdel)[SPAD] = reinterpret_cast<float(*)[SPAD]>(dsm);
    float (*sxp )[SPAD] = reinterpret_cast<float(*)[SPAD]>(dsm + CHL * SPAD * 4);
    float (*sgt )[SPAD] = reinterpret_cast<float(*)[SPAD]>(dsm + 2 * CHL * SPAD * 4);
    __half (*sout)[SCW] = reinterpret_cast<__half(*)[SCW]>(dsm + 3 * CHL * SPAD * 4);

    int tid   = threadIdx.x;
    int gidx0 = blockIdx.x * SCW;
    int chunk = gidx0 >> 12;
    int slot0 = gidx0 & (NSLOT - 1);
    int b     = slot0 >> 11;
    int ch0   = slot0 & (DINNER - 1);

    size_t base = (size_t)(b * SEQLEN + chunk * CHL) * DINNER + ch0;

#pragma unroll
    for (int it = 0; it < 4; it++) {
        int t  = (tid >> 4) + it * 16;
        int c4 = (tid & 15) * 4;
        *reinterpret_cast<float4*>(&sdel[t][c4]) =
            *reinterpret_cast<const float4*>(&g_delta[base + (size_t)t * DINNER + c4]);
        *reinterpret_cast<float4*>(&sxp[t][c4]) =
            *reinterpret_cast<const float4*>(&g_xproj[base + (size_t)t * DINNER + c4]);
        *reinterpret_cast<float4*>(&sgt[t][c4]) =
            *reinterpret_cast<const float4*>(&g_gate[base + (size_t)t * DINNER + c4]);
    }

    int grp  = tid >> 2;
    int s2   = tid & 3;
    int ch   = ch0 + grp;
    int slot = slot0 + grp;

    float As2[4], Bs[4], cs[4];
#pragma unroll
    for (int j = 0; j < 4; j++) {
        int s = s2 * 4 + j;
        As2[j] = -__expf(A_log[ch * DSTATE + s]) * LOG2E;
        Bs[j]  = B_mat[ch * DSTATE + s];
        cs[j]  = C_mat[s];
    }
    float Dch = D_vec[ch];

    // self-compose h0 from per-chunk (P,q) — float4 per chunk, uniform loop
    float h[4] = {0.f, 0.f, 0.f, 0.f};
    for (int j = 0; j < chunk; j++) {
        size_t o = ((size_t)(j << 12) + slot) * DSTATE + s2 * 4;
        float4 P4 = *reinterpret_cast<const float4*>(&g_P[o]);
        float4 q4 = *reinterpret_cast<const float4*>(&g_q[o]);
        h[0] = fmaf(P4.x, h[0], q4.x);
        h[1] = fmaf(P4.y, h[1], q4.y);
        h[2] = fmaf(P4.z, h[2], q4.z);
        h[3] = fmaf(P4.w, h[3], q4.w);
    }

    __syncthreads();

#pragma unroll 4
    for (int t = 0; t < CHL; t++) {
        float dt = sdel[t][grp];
        float xt = sxp[t][grp];
        float u  = dt * xt;
        float p  = 0.f;
#pragma unroll
        for (int j = 0; j < 4; j++) {
            float a = exp2f(As2[j] * dt);
            h[j] = fmaf(h[j], a, u * Bs[j]);
            p = fmaf(h[j], cs[j], p);
        }
        p += __shfl_xor_sync(0xffffffffu, p, 1);
        p += __shfl_xor_sync(0xffffffffu, p, 2);
        if (s2 == 0) {
            float v = sgt[t][grp] * (p + xt * Dch);
            sout[t][grp] = __float2half(v);
        }
    }
    __syncthreads();

    // cooperative store: 64 rows x 64 halves (128B/row), 4 threads/row,
    // each thread stores TWO uint4 (16 halves) -> full row covered.
    {
        int t = tid >> 2;
        int c = (tid & 3) * 16;
        *reinterpret_cast<uint4*>(&g_gss[base + (size_t)t * DINNER + c]) =
            *reinterpret_cast<const uint4*>(&sout[t][c]);
        *reinterpret_cast<uint4*>(&g_gss[base + (size_t)t * DINNER + c + 8]) =
            *reinterpret_cast<const uint4*>(&sout[t][c + 8]);
    }
}

#define SCANC_SMEM (3 * CHL * SPAD * 4 + CHL * SCW * 2)

// ---------------------------------------------------------------------------
extern "C" void kernel_launch(void* const* d_in, const int* in_sizes, int n_in,
                              void* d_out, int out_size)
{
    const float* x      = (const float*)d_in[0];
    const float* W_in   = (const float*)d_in[1];
    const float* b_in   = (const float*)d_in[2];
    const float* W_gate = (const float*)d_in[3];
    const float* b_gate = (const float*)d_in[4];
    const float* W_out  = (const float*)d_in[5];
    const float* b_out  = (const float*)d_in[6];
    const float* A_log  = (const float*)d_in[7];
    const float* B_mat  = (const float*)d_in[8];
    const float* C_mat  = (const float*)d_in[9];
    const float* D_vec  = (const float*)d_in[10];
    float* out = (float*)d_out;

    cudaFuncSetAttribute((const void*)gemm_mma<0, 128>,
                         cudaFuncAttributeMaxDynamicSharedMemorySize, SMEMT(128));
    cudaFuncSetAttribute((const void*)gemm_mma<2, 64>,
                         cudaFuncAttributeMaxDynamicSharedMemorySize, SMEMT(64));
    cudaFuncSetAttribute((const void*)scanC_kernel,
                         cudaFuncAttributeMaxDynamicSharedMemorySize, SCANC_SMEM);

    __half *xh, *wi, *wo, *gs;
    cudaGetSymbolAddress((void**)&xh, g_x);
    cudaGetSymbolAddress((void**)&wi, g_wi);
    cudaGetSymbolAddress((void**)&wo, g_wo);
    cudaGetSymbolAddress((void**)&gs, g_gss);

    const size_t WG_OFF = (size_t)2 * DINNER * DMODEL;

    // 1) fused fp32 -> fp16 converts
    conv_all_kernel<<<(CRT + 255) / 256, 256>>>(
        (const float4*)x, (const float4*)W_in, (const float4*)W_gate, (const float4*)W_out,
        (uint4*)xh, (uint4*)wi, (uint4*)(wi + WG_OFF), (uint4*)wo);

    // 2) fused in-proj + gate GEMM (N = 6144)
    gemm_mma<0, 128><<<dim3(NIN / 128, TOK / 128), 256, SMEMT(128)>>>(
        xh, wi, b_in, b_gate, nullptr, NIN, DMODEL);

    // 3) chunked selective scan (4 states/lane, 64 channels per CTA)
    scanA_kernel<<<(CHK * NSLOT) / SCW, 256>>>(A_log, B_mat);
    scanC_kernel<<<(CHK * NSLOT) / SCW, 256, SCANC_SMEM>>>(A_log, B_mat, C_mat, D_vec);

    // 4) out = gss @ W_out^T + b_out  (BM=64 -> 256 CTAs)
    gemm_mma<2, 64><<<dim3(DMODEL / 128, TOK / 64), 256, SMEMT(64)>>>(
        gs, wo, b_out, nullptr, out, DMODEL, DINNER);
}

// round 15
// speedup vs baseline: 2.1175x; 1.0089x over previous
#include <cuda_runtime.h>
#include <cuda_fp16.h>
#include <cstdint>

// Problem constants
#define TOK     2048
#define DMODEL  1024
#define DINNER  2048
#define DSTATE  16
#define SEQLEN  1024
#define NBATCH  2
#define NIN     (3 * DINNER)
#define CHK     16
#define CHL     (SEQLEN / CHK)
#define NSLOT   (NBATCH * DINNER)
#define NSS     (NSLOT * DSTATE)

#define LOG2E 1.4426950408889634f

// ---------------------------------------------------------------------------
// Device-global scratch (intermediates now fp16)
// ---------------------------------------------------------------------------
__device__ __half g_xproj[TOK * DINNER];
__device__ __half g_delta[TOK * DINNER];
__device__ __half g_gate [TOK * DINNER];

__device__ float g_P[CHK * NSS];
__device__ float g_q[CHK * NSS];

__device__ __half g_x  [TOK * DMODEL];
__device__ __half g_wi [NIN * DMODEL];
__device__ __half g_wo [DMODEL * DINNER];
__device__ __half g_gss[TOK * DINNER];

// ---------------------------------------------------------------------------
// PTX helpers
// ---------------------------------------------------------------------------
__device__ __forceinline__ uint32_t smem_u32(const void* p) {
    uint32_t a;
    asm("{ .reg .u64 t; cvta.to.shared.u64 t, %1; cvt.u32.u64 %0, t; }" : "=r"(a) : "l"(p));
    return a;
}
__device__ __forceinline__ void cpa16(uint32_t s, const void* g) {
    asm volatile("cp.async.cg.shared.global [%0], [%1], 16;" :: "r"(s), "l"(g) : "memory");
}
__device__ __forceinline__ void cpa_commit() {
    asm volatile("cp.async.commit_group;" ::: "memory");
}
template <int N>
__device__ __forceinline__ void cpa_wait() {
    asm volatile("cp.async.wait_group %0;" :: "n"(N) : "memory");
}
__device__ __forceinline__ void ldsm4(uint32_t& r0, uint32_t& r1, uint32_t& r2,
                                      uint32_t& r3, uint32_t a) {
    asm volatile("ldmatrix.sync.aligned.m8n8.x4.shared.b16 {%0,%1,%2,%3}, [%4];"
                 : "=r"(r0), "=r"(r1), "=r"(r2), "=r"(r3) : "r"(a));
}
__device__ __forceinline__ void mma16816(float* d, const uint32_t* a, const uint32_t* b) {
    asm volatile(
        "mma.sync.aligned.m16n8k16.row.col.f32.f16.f16.f32 "
        "{%0,%1,%2,%3}, {%4,%5,%6,%7}, {%8,%9}, {%0,%1,%2,%3};"
        : "+f"(d[0]), "+f"(d[1]), "+f"(d[2]), "+f"(d[3])
        : "r"(a[0]), "r"(a[1]), "r"(a[2]), "r"(a[3]), "r"(b[0]), "r"(b[1]));
}

// Fast exp on FMA/ALU pipes (GEMM epilogue sigmoid only)
__device__ __forceinline__ float fexp(float z) {
    float nf = rintf(z * LOG2E);
    float r  = fmaf(nf, -0.693145751953125f, z);
    r        = fmaf(nf, -1.42860677e-6f, r);
    float p  = 1.0f / 720.0f;
    p = fmaf(p, r, 1.0f / 120.0f);
    p = fmaf(p, r, 1.0f / 24.0f);
    p = fmaf(p, r, 1.0f / 6.0f);
    p = fmaf(p, r, 0.5f);
    p = fmaf(p, r, 1.0f);
    p = fmaf(p, r, 1.0f);
    float s = __int_as_float(((int)nf + 127) << 23);
    return p * s;
}

// ---------------------------------------------------------------------------
// GEMM SMEM: stage = A (BM rows) ++ W (128 rows), 80B rows, TRIPLE buffered
// ---------------------------------------------------------------------------
#define ROWB 80
#define SMEMT(BM) (3 * ((BM) * ROWB + 128 * ROWB) + 512)

template <int ROWS>
__device__ __forceinline__ void tile_cpasync(const __half* __restrict__ g,
                                             int rowBase, int kt, int ld,
                                             uint32_t sdst, int tid) {
#pragma unroll
    for (int i = 0; i < ROWS / 64; i++) {
        int seg = tid + i * 256;
        int r   = seg >> 2;
        int c   = seg & 3;
        cpa16(sdst + r * ROWB + c * 16,
              g + (size_t)(rowBase + r) * ld + kt + c * 8);
    }
}

// ---------------------------------------------------------------------------
// fp16 GEMM: C = A @ W^T + bias ; 3-stage cp.async pipeline, 1 sync/iter
// EPI 0 (N=6144): fp16 stores -> xproj | relu->delta | sigmoid->gate
// EPI 2: +bias -> Cout (fp32)
// ---------------------------------------------------------------------------
template <int EPI, int BM>
__global__ void __launch_bounds__(256, 2)
gemm_mma(const __half* __restrict__ A, const __half* __restrict__ W,
         const float* __restrict__ biasA, const float* __restrict__ biasB,
         float* __restrict__ Cout, int N, int K)
{
    constexpr int MI     = BM / 32;
    constexpr int ATILE  = BM * ROWB;
    constexpr int BTILE  = 128 * ROWB;
    constexpr int STAGE  = ATILE + BTILE;
    constexpr int BIASOF = 3 * STAGE;

    extern __shared__ char smem[];
    uint32_t sbase = smem_u32(smem);

    const int tid = threadIdx.x;
    const int wid = tid >> 5;
    const int l   = tid & 31;
    const int wm  = wid >> 2;
    const int wn  = wid & 3;
    const int mo  = wm * (BM / 2);
    const int no  = wn * 32;

    const int rowBase = blockIdx.y * BM;
    const int colBase = blockIdx.x * 128;

    if (tid < 128) {
        float bv;
        if (EPI == 0)
            bv = (colBase < 2 * DINNER) ? biasA[colBase + tid]
                                        : biasB[colBase - 2 * DINNER + tid];
        else
            bv = biasA[colBase + tid];
        *reinterpret_cast<float*>(smem + BIASOF + tid * 4) = bv;
    }

    const uint32_t aRow = (uint32_t)((mo + (l & 15)) * ROWB + ((l >> 4) * 16));
    const uint32_t bRow = (uint32_t)((no + (l & 7) + ((l & 16) ? 8 : 0)) * ROWB
                                     + (((l >> 3) & 1) * 16));

    float acc[MI][4][4];
#pragma unroll
    for (int mi = 0; mi < MI; mi++)
#pragma unroll
        for (int ni = 0; ni < 4; ni++)
#pragma unroll
            for (int r = 0; r < 4; r++) acc[mi][ni][r] = 0.0f;

    const int NC = K / 32;

    {
        tile_cpasync<BM >(A, rowBase, 0, K, sbase,         tid);
        tile_cpasync<128>(W, colBase, 0, K, sbase + ATILE, tid);
        cpa_commit();
        tile_cpasync<BM >(A, rowBase, 32, K, sbase + STAGE,         tid);
        tile_cpasync<128>(W, colBase, 32, K, sbase + STAGE + ATILE, tid);
        cpa_commit();
    }

    for (int c = 0; c < NC; c++) {
        if (c + 1 < NC) cpa_wait<1>();
        else            cpa_wait<0>();
        __syncthreads();

        if (c + 2 < NC) {
            uint32_t st = sbase + ((c + 2) % 3) * STAGE;
            int kt = (c + 2) * 32;
            tile_cpasync<BM >(A, rowBase, kt, K, st,         tid);
            tile_cpasync<128>(W, colBase, kt, K, st + ATILE, tid);
            cpa_commit();
        }

        uint32_t st = sbase + (c % 3) * STAGE;
#pragma unroll
        for (int ks = 0; ks < 2; ks++) {
            uint32_t ah[MI][4], bh[8];
#pragma unroll
            for (int mi = 0; mi < MI; mi++) {
                uint32_t ad = st + aRow + mi * (16 * ROWB) + ks * 32;
                ldsm4(ah[mi][0], ah[mi][1], ah[mi][2], ah[mi][3], ad);
            }
#pragma unroll
            for (int np = 0; np < 2; np++) {
                uint32_t bd = st + ATILE + bRow + np * (16 * ROWB) + ks * 32;
                ldsm4(bh[np * 4 + 0], bh[np * 4 + 1], bh[np * 4 + 2], bh[np * 4 + 3], bd);
            }
#pragma unroll
            for (int mi = 0; mi < MI; mi++)
#pragma unroll
                for (int ni = 0; ni < 4; ni++)
                    mma16816(acc[mi][ni], ah[mi], &bh[ni * 2]);
        }
    }

    __syncthreads();
    const float* sb = reinterpret_cast<const float*>(smem + BIASOF);
    const int g  = l >> 2;
    const int t4 = l & 3;
#pragma unroll
    for (int mi = 0; mi < MI; mi++) {
#pragma unroll
        for (int ni = 0; ni < 4; ni++) {
            int bc   = no + ni * 8 + 2 * t4;
            int col  = colBase + bc;
            int row0 = rowBase + mo + mi * 16 + g;
            int row1 = row0 + 8;
            float2 v0, v1;
            v0.x = acc[mi][ni][0] + sb[bc];
            v0.y = acc[mi][ni][1] + sb[bc + 1];
            v1.x = acc[mi][ni][2] + sb[bc];
            v1.y = acc[mi][ni][3] + sb[bc + 1];
            if (EPI == 0) {
                if (colBase < DINNER) {
                    *reinterpret_cast<__half2*>(&g_xproj[(size_t)row0 * DINNER + col]) =
                        __floats2half2_rn(v0.x, v0.y);
                    *reinterpret_cast<__half2*>(&g_xproj[(size_t)row1 * DINNER + col]) =
                        __floats2half2_rn(v1.x, v1.y);
                } else if (colBase < 2 * DINNER) {
                    int cc = col - DINNER;
                    *reinterpret_cast<__half2*>(&g_delta[(size_t)row0 * DINNER + cc]) =
                        __floats2half2_rn(fmaxf(v0.x, 0.f), fmaxf(v0.y, 0.f));
                    *reinterpret_cast<__half2*>(&g_delta[(size_t)row1 * DINNER + cc]) =
                        __floats2half2_rn(fmaxf(v1.x, 0.f), fmaxf(v1.y, 0.f));
                } else {
                    int cc = col - 2 * DINNER;
                    *reinterpret_cast<__half2*>(&g_gate[(size_t)row0 * DINNER + cc]) =
                        __floats2half2_rn(1.f / (1.f + fexp(-v0.x)),
                                          1.f / (1.f + fexp(-v0.y)));
                    *reinterpret_cast<__half2*>(&g_gate[(size_t)row1 * DINNER + cc]) =
                        __floats2half2_rn(1.f / (1.f + fexp(-v1.x)),
                                          1.f / (1.f + fexp(-v1.y)));
                }
            } else {
                *reinterpret_cast<float2*>(&Cout[(size_t)row0 * N + col]) = v0;
                *reinterpret_cast<float2*>(&Cout[(size_t)row1 * N + col]) = v1;
            }
        }
    }
}

// ---------------------------------------------------------------------------
// Fused fp32 -> fp16 convert for all four source arrays (one launch)
// ---------------------------------------------------------------------------
#define CR0 (TOK * DMODEL / 8)
#define CR1 (2 * DINNER * DMODEL / 8)
#define CR2 (DINNER * DMODEL / 8)
#define CR3 (DMODEL * DINNER / 8)
#define CRT (CR0 + CR1 + CR2 + CR3)

__global__ void __launch_bounds__(256)
conv_all_kernel(const float4* __restrict__ sx, const float4* __restrict__ swi,
                const float4* __restrict__ swg, const float4* __restrict__ swo,
                uint4* __restrict__ dx, uint4* __restrict__ dwi,
                uint4* __restrict__ dwg, uint4* __restrict__ dwo)
{
    int i = blockIdx.x * blockDim.x + threadIdx.x;
    if (i >= CRT) return;
    const float4* s; uint4* d; int off;
    if (i < CR0)                   { s = sx;  d = dx;  off = i; }
    else if (i < CR0 + CR1)        { s = swi; d = dwi; off = i - CR0; }
    else if (i < CR0 + CR1 + CR2)  { s = swg; d = dwg; off = i - CR0 - CR1; }
    else                           { s = swo; d = dwo; off = i - CR0 - CR1 - CR2; }
    float4 u = s[2 * off];
    float4 v = s[2 * off + 1];
    __half2 h0 = __floats2half2_rn(u.x, u.y);
    __half2 h1 = __floats2half2_rn(u.z, u.w);
    __half2 h2 = __floats2half2_rn(v.x, v.y);
    __half2 h3 = __floats2half2_rn(v.z, v.w);
    uint4 o;
    o.x = *reinterpret_cast<uint32_t*>(&h0);
    o.y = *reinterpret_cast<uint32_t*>(&h1);
    o.z = *reinterpret_cast<uint32_t*>(&h2);
    o.w = *reinterpret_cast<uint32_t*>(&h3);
    d[off] = o;
}

// ---------------------------------------------------------------------------
// Chunked selective scan, 4 states/lane, 64 channels/CTA, fp16 SMEM staging.
// Row stride 72 halves (144B = 9x16B): uint4-aligned every row, conflict-free.
// ---------------------------------------------------------------------------
#define SCW   64
#define SROWH 72

__global__ void __launch_bounds__(256)
scanA_kernel(const float* __restrict__ A_log, const float* __restrict__ B_mat)
{
    __shared__ __half sdel[CHL][SROWH];
    __shared__ __half sxp [CHL][SROWH];

    int tid   = threadIdx.x;
    int gidx0 = blockIdx.x * SCW;            // (chunk<<12) + slot0
    int chunk = gidx0 >> 12;
    int slot0 = gidx0 & (NSLOT - 1);
    int b     = slot0 >> 11;
    int ch0   = slot0 & (DINNER - 1);

    size_t base = (size_t)(b * SEQLEN + chunk * CHL) * DINNER + ch0;

    // stage 64 rows x 64 halves per array (8 uint4 per row)
#pragma unroll
    for (int it = 0; it < 2; it++) {
        int seg = tid + it * 256;            // 0..511
        int t   = seg >> 3;
        int c8  = (seg & 7) * 8;             // half index
        *reinterpret_cast<uint4*>(&sdel[t][c8]) =
            *reinterpret_cast<const uint4*>(&g_delta[base + (size_t)t * DINNER + c8]);
        *reinterpret_cast<uint4*>(&sxp[t][c8]) =
            *reinterpret_cast<const uint4*>(&g_xproj[base + (size_t)t * DINNER + c8]);
    }
    __syncthreads();

    int grp = tid >> 2;
    int s2  = tid & 3;
    int ch  = ch0 + grp;

    float As2[4], Bs[4];
#pragma unroll
    for (int j = 0; j < 4; j++) {
        int s = s2 * 4 + j;
        As2[j] = -__expf(A_log[ch * DSTATE + s]) * LOG2E;
        Bs[j]  = B_mat[ch * DSTATE + s];
    }

    float P[4] = {1.f, 1.f, 1.f, 1.f};
    float q[4] = {0.f, 0.f, 0.f, 0.f};
#pragma unroll 4
    for (int t = 0; t < CHL; t++) {
        float dt = __half2float(sdel[t][grp]);
        float xt = __half2float(sxp[t][grp]);
        float u  = dt * xt;
#pragma unroll
        for (int j = 0; j < 4; j++) {
            float a = exp2f(As2[j] * dt);
            q[j] = fmaf(q[j], a, u * Bs[j]);
            P[j] *= a;
        }
    }
    size_t o = (size_t)(gidx0 + grp) * DSTATE + s2 * 4;
    *reinterpret_cast<float4*>(&g_P[o]) = make_float4(P[0], P[1], P[2], P[3]);
    *reinterpret_cast<float4*>(&g_q[o]) = make_float4(q[0], q[1], q[2], q[3]);
}

__global__ void __launch_bounds__(256)
scanC_kernel(const float* __restrict__ A_log, const float* __restrict__ B_mat,
             const float* __restrict__ C_mat, const float* __restrict__ D_vec)
{
    __shared__ __half sdel[CHL][SROWH];
    __shared__ __half sxp [CHL][SROWH];
    __shared__ __half sgt [CHL][SROWH];
    __shared__ __half sout[CHL][SCW];

    int tid   = threadIdx.x;
    int gidx0 = blockIdx.x * SCW;
    int chunk = gidx0 >> 12;
    int slot0 = gidx0 & (NSLOT - 1);
    int b     = slot0 >> 11;
    int ch0   = slot0 & (DINNER - 1);

    size_t base = (size_t)(b * SEQLEN + chunk * CHL) * DINNER + ch0;

#pragma unroll
    for (int it = 0; it < 2; it++) {
        int seg = tid + it * 256;
        int t   = seg >> 3;
        int c8  = (seg & 7) * 8;
        *reinterpret_cast<uint4*>(&sdel[t][c8]) =
            *reinterpret_cast<const uint4*>(&g_delta[base + (size_t)t * DINNER + c8]);
        *reinterpret_cast<uint4*>(&sxp[t][c8]) =
            *reinterpret_cast<const uint4*>(&g_xproj[base + (size_t)t * DINNER + c8]);
        *reinterpret_cast<uint4*>(&sgt[t][c8]) =
            *reinterpret_cast<const uint4*>(&g_gate[base + (size_t)t * DINNER + c8]);
    }

    int grp  = tid >> 2;
    int s2   = tid & 3;
    int ch   = ch0 + grp;
    int slot = slot0 + grp;

    float As2[4], Bs[4], cs[4];
#pragma unroll
    for (int j = 0; j < 4; j++) {
        int s = s2 * 4 + j;
        As2[j] = -__expf(A_log[ch * DSTATE + s]) * LOG2E;
        Bs[j]  = B_mat[ch * DSTATE + s];
        cs[j]  = C_mat[s];
    }
    float Dch = D_vec[ch];

    // self-compose h0 from per-chunk (P,q)
    float h[4] = {0.f, 0.f, 0.f, 0.f};
    for (int j = 0; j < chunk; j++) {
        size_t o = ((size_t)(j << 12) + slot) * DSTATE + s2 * 4;
        float4 P4 = *reinterpret_cast<const float4*>(&g_P[o]);
        float4 q4 = *reinterpret_cast<const float4*>(&g_q[o]);
        h[0] = fmaf(P4.x, h[0], q4.x);
        h[1] = fmaf(P4.y, h[1], q4.y);
        h[2] = fmaf(P4.z, h[2], q4.z);
        h[3] = fmaf(P4.w, h[3], q4.w);
    }

    __syncthreads();

#pragma unroll 4
    for (int t = 0; t < CHL; t++) {
        float dt = __half2float(sdel[t][grp]);
        float xt = __half2float(sxp[t][grp]);
        float u  = dt * xt;
        float p  = 0.f;
#pragma unroll
        for (int j = 0; j < 4; j++) {
            float a = exp2f(As2[j] * dt);
            h[j] = fmaf(h[j], a, u * Bs[j]);
            p = fmaf(h[j], cs[j], p);
        }
        p += __shfl_xor_sync(0xffffffffu, p, 1);
        p += __shfl_xor_sync(0xffffffffu, p, 2);
        if (s2 == 0) {
            float v = __half2float(sgt[t][grp]) * (p + xt * Dch);
            sout[t][grp] = __float2half(v);
        }
    }
    __syncthreads();

    // cooperative store: 64 rows x 64 halves (128B/row), full coverage
    {
        int t = tid >> 2;
        int c = (tid & 3) * 16;
        *reinterpret_cast<uint4*>(&g_gss[base + (size_t)t * DINNER + c]) =
            *reinterpret_cast<const uint4*>(&sout[t][c]);
        *reinterpret_cast<uint4*>(&g_gss[base + (size_t)t * DINNER + c + 8]) =
            *reinterpret_cast<const uint4*>(&sout[t][c + 8]);
    }
}

// ---------------------------------------------------------------------------
extern "C" void kernel_launch(void* const* d_in, const int* in_sizes, int n_in,
                              void* d_out, int out_size)
{
    const float* x      = (const float*)d_in[0];
    const float* W_in   = (const float*)d_in[1];
    const float* b_in   = (const float*)d_in[2];
    const float* W_gate = (const float*)d_in[3];
    const float* b_gate = (const float*)d_in[4];
    const float* W_out  = (const float*)d_in[5];
    const float* b_out  = (const float*)d_in[6];
    const float* A_log  = (const float*)d_in[7];
    const float* B_mat  = (const float*)d_in[8];
    const float* C_mat  = (const float*)d_in[9];
    const float* D_vec  = (const float*)d_in[10];
    float* out = (float*)d_out;

    cudaFuncSetAttribute((const void*)gemm_mma<0, 128>,
                         cudaFuncAttributeMaxDynamicSharedMemorySize, SMEMT(128));
    cudaFuncSetAttribute((const void*)gemm_mma<2, 64>,
                         cudaFuncAttributeMaxDynamicSharedMemorySize, SMEMT(64));

    __half *xh, *wi, *wo, *gs;
    cudaGetSymbolAddress((void**)&xh, g_x);
    cudaGetSymbolAddress((void**)&wi, g_wi);
    cudaGetSymbolAddress((void**)&wo, g_wo);
    cudaGetSymbolAddress((void**)&gs, g_gss);

    const size_t WG_OFF = (size_t)2 * DINNER * DMODEL;

    // 1) fused fp32 -> fp16 converts
    conv_all_kernel<<<(CRT + 255) / 256, 256>>>(
        (const float4*)x, (const float4*)W_in, (const float4*)W_gate, (const float4*)W_out,
        (uint4*)xh, (uint4*)wi, (uint4*)(wi + WG_OFF), (uint4*)wo);

    // 2) fused in-proj + gate GEMM (N = 6144), fp16 epilogue
    gemm_mma<0, 128><<<dim3(NIN / 128, TOK / 128), 256, SMEMT(128)>>>(
        xh, wi, b_in, b_gate, nullptr, NIN, DMODEL);

    // 3) chunked selective scan (4 states/lane, 64 channels per CTA, fp16 staging)
    scanA_kernel<<<(CHK * NSLOT) / SCW, 256>>>(A_log, B_mat);
    scanC_kernel<<<(CHK * NSLOT) / SCW, 256>>>(A_log, B_mat, C_mat, D_vec);

    // 4) out = gss @ W_out^T + b_out  (BM=64 -> 256 CTAs)
    gemm_mma<2, 64><<<dim3(DMODEL / 128, TOK / 64), 256, SMEMT(64)>>>(
        gs, wo, b_out, nullptr, out, DMODEL, DINNER);
}